// round 3
// baseline (speedup 1.0000x reference)
#include <cuda_runtime.h>

// ---------------- problem constants ----------------
constexpr int NN   = 50000;   // nodes
constexpr int NE   = 512000;  // edges
constexpr int HD   = 128;     // hidden
constexpr int EDIM = 32;      // edge dim
constexpr int NL   = 10;      // GINE layers
constexpr int NG   = 64;      // graphs
constexpr int NOUT = 10;
constexpr float EPSF  = 1e-5f;
constexpr float SLOPE = 0.2f;

typedef unsigned long long u64;
typedef unsigned int u32;

// ---------------- helpers ----------------
__device__ __forceinline__ u64 pack2(float lo, float hi) {
    u64 r; asm("mov.b64 %0,{%1,%2};" : "=l"(r) : "f"(lo), "f"(hi)); return r;
}
__device__ __forceinline__ void unpack2(u64 v, float& lo, float& hi) {
    asm("mov.b64 {%0,%1},%2;" : "=f"(lo), "=f"(hi) : "l"(v));
}
__device__ __forceinline__ u64 ffma2(u64 a, u64 b, u64 c) {
    u64 d; asm("fma.rn.f32x2 %0,%1,%2,%3;" : "=l"(d) : "l"(a), "l"(b), "l"(c)); return d;
}
__device__ __forceinline__ float lrelu(float v) { return v < 0.f ? SLOPE * v : v; }
// order-preserving float<->uint for atomicMax on floats (incl. negatives)
__device__ __forceinline__ u32 ford(float f) {
    u32 u = __float_as_uint(f);
    return (u & 0x80000000u) ? ~u : (u | 0x80000000u);
}
__device__ __forceinline__ float funord(u32 u) {
    return __uint_as_float((u & 0x80000000u) ? (u ^ 0x80000000u) : ~u);
}

// ---------------- device scratch (no allocs allowed) ----------------
__device__ __align__(16) float g_hn[NN * HD];
__device__ __align__(16) float g_agg[NN * HD];
__device__ __align__(16) float g_t[NN * HD];
__device__ __align__(16) float g_o[NN * HD];
__device__ __align__(16) float g_x[NN * HD];
__device__ __align__(16) float g_hfeat[NN * 4 * HD];   // GAT features [N,4,128]
__device__ __align__(16) float g_eagg[NN * EDIM];
__device__           float g_degf[NN];
__device__           int   g_deg[NN];
__device__           int   g_rowptr[NN + 1];
__device__           int   g_cursor[NN];
__device__           int   g_csrc[NE];
__device__           int   g_ceid[NE];
__device__ __align__(16) float g_as[NN * 4];
__device__ __align__(16) float g_ad[NN * 4];
__device__ __align__(16) u32   g_amax[NN * 4];
__device__ __align__(16) float g_den[NN * 4];
__device__ __align__(16) float g_bnsum[HD];
__device__ __align__(16) float g_bnsq[HD];
__device__ __align__(16) float g_scale[HD];
__device__ __align__(16) float g_shift[HD];
__device__ __align__(16) float g_pool[NG * HD];

// Device-side buffer dispatch — keeps kernel_launch free of any host-side
// symbol-address API (nothing but kernel launches enters the graph).
enum BufTag { T_NONE = 0, T_HN, T_AGG, T_T, T_O, T_X, T_HF, T_EA, T_DEGF };
__device__ __forceinline__ float* bufptr(int t) {
    switch (t) {
        case T_HN:   return g_hn;
        case T_AGG:  return g_agg;
        case T_T:    return g_t;
        case T_O:    return g_o;
        case T_X:    return g_x;
        case T_HF:   return g_hfeat;
        case T_EA:   return g_eagg;
        case T_DEGF: return g_degf;
        default:     return nullptr;
    }
}

// ---------------- SGEMM: C[M,Nc] = A[M,K] @ B[K,Nc] (+ rowscale*bias) (+relu) ----------------
// 128x128 block tile, BK=8, 256 threads, 8x8 per-thread tile, packed f32x2 FMA.
// A is either an external pointer (Aext) or a scratch tag; C/rowscale are tags.
template<bool RELU>
__global__ __launch_bounds__(256, 2)
void sgemm(const float* __restrict__ Aext, int Atag, const float* __restrict__ B,
           const float* __restrict__ bias, int rstag, int Ctag,
           int M, int K, int ldb, int ldc)
{
    __shared__ __align__(16) float As[8][128];
    __shared__ __align__(16) float Bs[8][128];

    const float* A = Aext ? Aext : bufptr(Atag);
    const float* rowscale = rstag ? bufptr(rstag) : nullptr;
    float* C = bufptr(Ctag);

    int tid  = threadIdx.x;
    int row0 = blockIdx.x * 128;
    int col0 = blockIdx.y * 128;

    int arow = tid >> 1;           // 0..127
    int akq  = (tid & 1) * 4;      // 0 or 4
    int brow = tid >> 5;           // 0..7
    int bcol = (tid & 31) * 4;

    int tm0 = (tid >> 4) * 8;
    int tn0 = (tid & 15) * 8;

    u64 acc[4][8];
#pragma unroll
    for (int i = 0; i < 4; i++)
#pragma unroll
        for (int j = 0; j < 8; j++) acc[i][j] = pack2(0.f, 0.f);

    const float* aptr  = A + (size_t)(row0 + arow) * K + akq;
    bool avalid = (row0 + arow) < M;

    for (int k0 = 0; k0 < K; k0 += 8) {
        float4 av = avalid ? *(const float4*)(aptr + k0) : make_float4(0.f, 0.f, 0.f, 0.f);
        As[akq + 0][arow] = av.x;
        As[akq + 1][arow] = av.y;
        As[akq + 2][arow] = av.z;
        As[akq + 3][arow] = av.w;
        float4 bv = *(const float4*)(B + (size_t)(k0 + brow) * ldb + col0 + bcol);
        *(float4*)&Bs[brow][bcol] = bv;
        __syncthreads();
#pragma unroll
        for (int k = 0; k < 8; k++) {
            float4 a0 = *(const float4*)&As[k][tm0];
            float4 a1 = *(const float4*)&As[k][tm0 + 4];
            float4 b0 = *(const float4*)&Bs[k][tn0];
            float4 b1 = *(const float4*)&Bs[k][tn0 + 4];
            u64 ap[4] = { pack2(a0.x, a0.y), pack2(a0.z, a0.w),
                          pack2(a1.x, a1.y), pack2(a1.z, a1.w) };
            u64 bb[8] = { pack2(b0.x, b0.x), pack2(b0.y, b0.y), pack2(b0.z, b0.z), pack2(b0.w, b0.w),
                          pack2(b1.x, b1.x), pack2(b1.y, b1.y), pack2(b1.z, b1.z), pack2(b1.w, b1.w) };
#pragma unroll
            for (int i = 0; i < 4; i++)
#pragma unroll
                for (int j = 0; j < 8; j++) acc[i][j] = ffma2(ap[i], bb[j], acc[i][j]);
        }
        __syncthreads();
    }

    float bb_[8];
#pragma unroll
    for (int j = 0; j < 8; j++) bb_[j] = bias ? bias[col0 + tn0 + j] : 0.f;

#pragma unroll
    for (int i = 0; i < 4; i++) {
        float lo[8], hi[8];
#pragma unroll
        for (int j = 0; j < 8; j++) unpack2(acc[i][j], lo[j], hi[j]);
        int r0 = row0 + tm0 + 2 * i;
        int r1 = r0 + 1;
        if (r0 < M) {
            float rs = rowscale ? rowscale[r0] : 1.f;
            float4 v0, v1;
            v0.x = lo[0] + rs * bb_[0]; v0.y = lo[1] + rs * bb_[1];
            v0.z = lo[2] + rs * bb_[2]; v0.w = lo[3] + rs * bb_[3];
            v1.x = lo[4] + rs * bb_[4]; v1.y = lo[5] + rs * bb_[5];
            v1.z = lo[6] + rs * bb_[6]; v1.w = lo[7] + rs * bb_[7];
            if (RELU) {
                v0.x = fmaxf(v0.x, 0.f); v0.y = fmaxf(v0.y, 0.f); v0.z = fmaxf(v0.z, 0.f); v0.w = fmaxf(v0.w, 0.f);
                v1.x = fmaxf(v1.x, 0.f); v1.y = fmaxf(v1.y, 0.f); v1.z = fmaxf(v1.z, 0.f); v1.w = fmaxf(v1.w, 0.f);
            }
            *(float4*)&C[(size_t)r0 * ldc + col0 + tn0]     = v0;
            *(float4*)&C[(size_t)r0 * ldc + col0 + tn0 + 4] = v1;
        }
        if (r1 < M) {
            float rs = rowscale ? rowscale[r1] : 1.f;
            float4 v0, v1;
            v0.x = hi[0] + rs * bb_[0]; v0.y = hi[1] + rs * bb_[1];
            v0.z = hi[2] + rs * bb_[2]; v0.w = hi[3] + rs * bb_[3];
            v1.x = hi[4] + rs * bb_[4]; v1.y = hi[5] + rs * bb_[5];
            v1.z = hi[6] + rs * bb_[6]; v1.w = hi[7] + rs * bb_[7];
            if (RELU) {
                v0.x = fmaxf(v0.x, 0.f); v0.y = fmaxf(v0.y, 0.f); v0.z = fmaxf(v0.z, 0.f); v0.w = fmaxf(v0.w, 0.f);
                v1.x = fmaxf(v1.x, 0.f); v1.y = fmaxf(v1.y, 0.f); v1.z = fmaxf(v1.z, 0.f); v1.w = fmaxf(v1.w, 0.f);
            }
            *(float4*)&C[(size_t)r1 * ldc + col0 + tn0]     = v0;
            *(float4*)&C[(size_t)r1 * ldc + col0 + tn0 + 4] = v1;
        }
    }
}

// ---------------- CSR build ----------------
__global__ void zero_deg() {
    int i = blockIdx.x * blockDim.x + threadIdx.x;
    if (i < NN) g_deg[i] = 0;
}
__global__ void hist_kernel(const int* __restrict__ ei) {
    int e = blockIdx.x * blockDim.x + threadIdx.x;
    if (e < NE) atomicAdd(&g_deg[ei[NE + e]], 1);
}
__global__ void scan_kernel() {
    __shared__ int sh[1024];
    __shared__ int carry;
    int tid = threadIdx.x;
    if (tid == 0) carry = 0;
    __syncthreads();
    for (int base = 0; base < NN; base += 1024) {
        int i = base + tid;
        int v = (i < NN) ? g_deg[i] : 0;
        sh[tid] = v;
        __syncthreads();
        for (int off = 1; off < 1024; off <<= 1) {
            int t = (tid >= off) ? sh[tid - off] : 0;
            __syncthreads();
            sh[tid] += t;
            __syncthreads();
        }
        int incl = sh[tid];
        int excl = incl - v + carry;
        if (i < NN) {
            g_rowptr[i] = excl;
            g_cursor[i] = excl;
            g_degf[i]   = (float)v;
        }
        __syncthreads();
        if (tid == 1023) carry += incl;
        __syncthreads();
    }
    if (tid == 0) g_rowptr[NN] = carry;
}
__global__ void scatter_kernel(const int* __restrict__ ei) {
    int e = blockIdx.x * blockDim.x + threadIdx.x;
    if (e >= NE) return;
    int s = ei[e], d = ei[NE + e];
    int p = atomicAdd(&g_cursor[d], 1);
    g_csrc[p] = s;
    g_ceid[p] = e;
}
// Eagg[n,k] = sum over in-edges of edge_attr[e,k]  (layer-invariant)
__global__ void eagg_kernel(const float* __restrict__ edge_attr) {
    int w = (blockIdx.x * blockDim.x + threadIdx.x) >> 5;
    if (w >= NN) return;
    int lane = threadIdx.x & 31;
    float acc = 0.f;
    int p0 = g_rowptr[w], p1 = g_rowptr[w + 1];
    for (int p = p0; p < p1; p++) {
        int e = g_ceid[p];
        acc += edge_attr[e * EDIM + lane];
    }
    g_eagg[w * EDIM + lane] = acc;
}

// ---------------- GINE aggregation: agg[n] += sum hn[src] (CSR, atomic-free) ----------------
__global__ void gine_aggregate() {
    int w = (blockIdx.x * blockDim.x + threadIdx.x) >> 5;
    if (w >= NN) return;
    int lane = threadIdx.x & 31;
    float4 acc = *(const float4*)&g_agg[w * HD + lane * 4];
    int p0 = g_rowptr[w], p1 = g_rowptr[w + 1];
    for (int p = p0; p < p1; p++) {
        int s = g_csrc[p];
        const float4 v = *(const float4*)&g_hn[s * HD + lane * 4];
        acc.x += v.x; acc.y += v.y; acc.z += v.z; acc.w += v.w;
    }
    *(float4*)&g_agg[w * HD + lane * 4] = acc;
}

// ---------------- BatchNorm ----------------
__global__ void bn_zero() {
    int c = threadIdx.x;
    if (c < HD) { g_bnsum[c] = 0.f; g_bnsq[c] = 0.f; }
}
__global__ void bn_reduce() {
    int c = threadIdx.x;
    float s = 0.f, q = 0.f;
    for (int r = blockIdx.x; r < NN; r += gridDim.x) {
        float v = g_o[r * HD + c];
        s += v; q += v * v;
    }
    atomicAdd(&g_bnsum[c], s);
    atomicAdd(&g_bnsq[c], q);
}
__global__ void bn_final(const float* __restrict__ gamma, const float* __restrict__ beta) {
    int c = threadIdx.x;
    if (c >= HD) return;
    float mu  = g_bnsum[c] / (float)NN;
    float var = g_bnsq[c] / (float)NN - mu * mu;
    float sc  = gamma[c] * rsqrtf(var + EPSF);
    g_scale[c] = sc;
    g_shift[c] = beta[c] - mu * sc;
}
__global__ void norm_relu() {
    int i = blockIdx.x * blockDim.x + threadIdx.x;  // over N*32 float4s
    if (i >= NN * 32) return;
    float4 v = ((const float4*)g_o)[i];
    int c = (i & 31) * 4;
    float4 sc = *(const float4*)&g_scale[c];
    float4 sh = *(const float4*)&g_shift[c];
    v.x = fmaxf(v.x * sc.x + sh.x, 0.f);
    v.y = fmaxf(v.y * sc.y + sh.y, 0.f);
    v.z = fmaxf(v.z * sc.z + sh.z, 0.f);
    v.w = fmaxf(v.w * sc.w + sh.w, 0.f);
    ((float4*)g_x)[i] = v;
}

// ---------------- GAT ----------------
__global__ void gat_node1(const float* __restrict__ att_src, const float* __restrict__ att_dst) {
    int n = (blockIdx.x * blockDim.x + threadIdx.x) >> 5;
    if (n >= NN) return;
    int lane = threadIdx.x & 31;
    float s[4], d[4];
#pragma unroll
    for (int h = 0; h < 4; h++) {
        float4 hv = *(const float4*)&g_hfeat[n * 512 + h * 128 + lane * 4];
        float4 a1 = *(const float4*)&att_src[h * 128 + lane * 4];
        float4 a2 = *(const float4*)&att_dst[h * 128 + lane * 4];
        float ps = hv.x * a1.x + hv.y * a1.y + hv.z * a1.z + hv.w * a1.w;
        float pd = hv.x * a2.x + hv.y * a2.y + hv.z * a2.z + hv.w * a2.w;
#pragma unroll
        for (int off = 16; off > 0; off >>= 1) {
            ps += __shfl_xor_sync(0xffffffffu, ps, off);
            pd += __shfl_xor_sync(0xffffffffu, pd, off);
        }
        s[h] = ps; d[h] = pd;
    }
    if (lane == 0) {
#pragma unroll
        for (int h = 0; h < 4; h++) {
            g_as[n * 4 + h] = s[h];
            g_ad[n * 4 + h] = d[h];
            g_amax[n * 4 + h] = ford(lrelu(s[h] + d[h]));   // self-loop seeds the max
        }
    }
}
__global__ void gat_edge1(const int* __restrict__ ei) {
    int e = blockIdx.x * blockDim.x + threadIdx.x;
    if (e >= NE) return;
    int s = ei[e], d = ei[NE + e];
    float4 a = *(const float4*)&g_as[s * 4];
    float4 b = *(const float4*)&g_ad[d * 4];
    atomicMax(&g_amax[d * 4 + 0], ford(lrelu(a.x + b.x)));
    atomicMax(&g_amax[d * 4 + 1], ford(lrelu(a.y + b.y)));
    atomicMax(&g_amax[d * 4 + 2], ford(lrelu(a.z + b.z)));
    atomicMax(&g_amax[d * 4 + 3], ford(lrelu(a.w + b.w)));
}
__global__ void gat_node2() {  // denom init = self-loop term
    int n = blockIdx.x * blockDim.x + threadIdx.x;
    if (n >= NN) return;
    float4 a = *(const float4*)&g_as[n * 4];
    float4 b = *(const float4*)&g_ad[n * 4];
    uint4 mu = *(const uint4*)&g_amax[n * 4];
    float4 den;
    den.x = __expf(lrelu(a.x + b.x) - funord(mu.x));
    den.y = __expf(lrelu(a.y + b.y) - funord(mu.y));
    den.z = __expf(lrelu(a.z + b.z) - funord(mu.z));
    den.w = __expf(lrelu(a.w + b.w) - funord(mu.w));
    *(float4*)&g_den[n * 4] = den;
}
__global__ void gat_edge2(const int* __restrict__ ei) {
    int e = blockIdx.x * blockDim.x + threadIdx.x;
    if (e >= NE) return;
    int s = ei[e], d = ei[NE + e];
    float4 a = *(const float4*)&g_as[s * 4];
    float4 b = *(const float4*)&g_ad[d * 4];
    uint4 mu = *(const uint4*)&g_amax[d * 4];
    atomicAdd(&g_den[d * 4 + 0], __expf(lrelu(a.x + b.x) - funord(mu.x)));
    atomicAdd(&g_den[d * 4 + 1], __expf(lrelu(a.y + b.y) - funord(mu.y)));
    atomicAdd(&g_den[d * 4 + 2], __expf(lrelu(a.z + b.z) - funord(mu.z)));
    atomicAdd(&g_den[d * 4 + 3], __expf(lrelu(a.w + b.w) - funord(mu.w)));
}
__global__ void gat_node3(const float* __restrict__ bg) {
    int n = (blockIdx.x * blockDim.x + threadIdx.x) >> 5;
    if (n >= NN) return;
    int lane = threadIdx.x & 31;
    float4 adn = *(const float4*)&g_ad[n * 4];
    float4 asn = *(const float4*)&g_as[n * 4];
    uint4 mu = *(const uint4*)&g_amax[n * 4];
    float m0 = funord(mu.x), m1 = funord(mu.y), m2 = funord(mu.z), m3 = funord(mu.w);
    float4 den = *(const float4*)&g_den[n * 4];
    float i0 = 1.f / den.x, i1 = 1.f / den.y, i2 = 1.f / den.z, i3 = 1.f / den.w;

    float w0 = __expf(lrelu(asn.x + adn.x) - m0) * i0;
    float w1 = __expf(lrelu(asn.y + adn.y) - m1) * i1;
    float w2 = __expf(lrelu(asn.z + adn.z) - m2) * i2;
    float w3 = __expf(lrelu(asn.w + adn.w) - m3) * i3;

    int base = n * 512 + lane * 4;
    float4 h0 = *(const float4*)&g_hfeat[base];
    float4 h1 = *(const float4*)&g_hfeat[base + 128];
    float4 h2 = *(const float4*)&g_hfeat[base + 256];
    float4 h3 = *(const float4*)&g_hfeat[base + 384];
    float4 A0 = { w0 * h0.x, w0 * h0.y, w0 * h0.z, w0 * h0.w };
    float4 A1 = { w1 * h1.x, w1 * h1.y, w1 * h1.z, w1 * h1.w };
    float4 A2 = { w2 * h2.x, w2 * h2.y, w2 * h2.z, w2 * h2.w };
    float4 A3 = { w3 * h3.x, w3 * h3.y, w3 * h3.z, w3 * h3.w };

    int p0 = g_rowptr[n], p1 = g_rowptr[n + 1];
    for (int p = p0; p < p1; p++) {
        int s = g_csrc[p];
        float4 ass = *(const float4*)&g_as[s * 4];
        float e0 = __expf(lrelu(ass.x + adn.x) - m0) * i0;
        float e1 = __expf(lrelu(ass.y + adn.y) - m1) * i1;
        float e2 = __expf(lrelu(ass.z + adn.z) - m2) * i2;
        float e3 = __expf(lrelu(ass.w + adn.w) - m3) * i3;
        int sb = s * 512 + lane * 4;
        float4 v0 = *(const float4*)&g_hfeat[sb];
        float4 v1 = *(const float4*)&g_hfeat[sb + 128];
        float4 v2 = *(const float4*)&g_hfeat[sb + 256];
        float4 v3 = *(const float4*)&g_hfeat[sb + 384];
        A0.x += e0 * v0.x; A0.y += e0 * v0.y; A0.z += e0 * v0.z; A0.w += e0 * v0.w;
        A1.x += e1 * v1.x; A1.y += e1 * v1.y; A1.z += e1 * v1.z; A1.w += e1 * v1.w;
        A2.x += e2 * v2.x; A2.y += e2 * v2.y; A2.z += e2 * v2.z; A2.w += e2 * v2.w;
        A3.x += e3 * v3.x; A3.y += e3 * v3.y; A3.z += e3 * v3.z; A3.w += e3 * v3.w;
    }
    float4 bg4 = *(const float4*)&bg[lane * 4];
    float4 o4;
    o4.x = (A0.x + A1.x + A2.x + A3.x) * 0.25f + bg4.x;
    o4.y = (A0.y + A1.y + A2.y + A3.y) * 0.25f + bg4.y;
    o4.z = (A0.z + A1.z + A2.z + A3.z) * 0.25f + bg4.z;
    o4.w = (A0.w + A1.w + A2.w + A3.w) * 0.25f + bg4.w;
    *(float4*)&g_x[n * HD + lane * 4] = o4;
}

// ---------------- pooling + fc (batch sorted -> per-graph range, no atomics) ----------------
__device__ __forceinline__ int lbound(const int* a, int n, int key) {
    int lo = 0, hi = n;
    while (lo < hi) { int mid = (lo + hi) >> 1; if (a[mid] < key) lo = mid + 1; else hi = mid; }
    return lo;
}
__global__ void pool_kernel(const int* __restrict__ batch) {
    int g = blockIdx.x;
    int c = threadIdx.x;   // 128 threads
    __shared__ int slo, shi;
    if (c == 0) { slo = lbound(batch, NN, g); shi = lbound(batch, NN, g + 1); }
    __syncthreads();
    int lo = slo, hi = shi;
    float a0 = 0.f, a1 = 0.f, a2 = 0.f, a3 = 0.f;
    int n = lo;
    for (; n + 4 <= hi; n += 4) {
        a0 += g_x[n * HD + c];
        a1 += g_x[(n + 1) * HD + c];
        a2 += g_x[(n + 2) * HD + c];
        a3 += g_x[(n + 3) * HD + c];
    }
    for (; n < hi; n++) a0 += g_x[n * HD + c];
    float s = (a0 + a1) + (a2 + a3);
    g_pool[g * HD + c] = s / fmaxf((float)(hi - lo), 1.f);
}
__global__ void final_kernel(const float* __restrict__ Wfc, const float* __restrict__ bfc,
                             float* __restrict__ out) {
    int idx = blockIdx.x * blockDim.x + threadIdx.x;
    if (idx >= NG * NOUT) return;
    int g = idx / NOUT, o = idx % NOUT;
    float s = bfc[o];
#pragma unroll 8
    for (int k = 0; k < HD; k++) s += g_pool[g * HD + k] * Wfc[k * NOUT + o];
    out[idx] = s;
}

// ---------------- driver (kernel launches ONLY — graph-capture safe) ----------------
extern "C" void kernel_launch(void* const* d_in, const int* in_sizes, int n_in,
                              void* d_out, int out_size) {
    const float* x_in      = (const float*)d_in[0];
    const float* edge_attr = (const float*)d_in[1];
    const int*   ei        = (const int*)d_in[2];
    const int*   batch     = (const int*)d_in[3];
    const float* Wn   = (const float*)d_in[4];
    const float* bn_b = (const float*)d_in[5];
    const float* We   = (const float*)d_in[6];
    const float* be_b = (const float*)d_in[7];
    const float* W1   = (const float*)d_in[8];
    const float* b1   = (const float*)d_in[9];
    const float* W2   = (const float*)d_in[10];
    const float* b2   = (const float*)d_in[11];
    const float* gamma= (const float*)d_in[12];
    const float* beta = (const float*)d_in[13];
    const float* Wg   = (const float*)d_in[14];
    const float* att_src = (const float*)d_in[15];
    const float* att_dst = (const float*)d_in[16];
    const float* bg   = (const float*)d_in[17];
    const float* Wfc  = (const float*)d_in[18];
    const float* bfc  = (const float*)d_in[19];
    float* out = (float*)d_out;

    const int TB = 256;
    const int NODE_BLK = (NN + TB - 1) / TB;                 // 196
    const int EDGE_BLK = (NE + TB - 1) / TB;                 // 2000
    const int WARP_BLK = (NN * 32 + TB - 1) / TB;            // 6250
    const dim3 GEMM_G(391, 1);
    const dim3 GEMM_G4(391, 4);

    // ---- graph structure (layer-invariant) ----
    zero_deg<<<NODE_BLK, TB>>>();
    hist_kernel<<<EDGE_BLK, TB>>>(ei);
    scan_kernel<<<1, 1024>>>();
    scatter_kernel<<<EDGE_BLK, TB>>>(ei);
    eagg_kernel<<<WARP_BLK, TB>>>(edge_attr);

    // ---- 10 GINE layers ----
    for (int l = 0; l < NL; l++) {
        // hn = x @ Wn + bn_b
        sgemm<false><<<GEMM_G, TB>>>((l == 0) ? x_in : nullptr, T_X,
                                     Wn + (size_t)l * HD * HD, bn_b + l * HD,
                                     T_NONE, T_HN, NN, HD, HD, HD);
        // agg = Eagg @ We + deg*be_b   (edge-encoder term, algebraically hoisted)
        sgemm<false><<<GEMM_G, TB>>>(nullptr, T_EA,
                                     We + (size_t)l * EDIM * HD, be_b + l * HD,
                                     T_DEGF, T_AGG, NN, EDIM, HD, HD);
        // agg += sum_{in-edges} hn[src]
        gine_aggregate<<<WARP_BLK, TB>>>();
        // t = relu(agg @ W1 + b1)
        sgemm<true ><<<GEMM_G, TB>>>(nullptr, T_AGG,
                                     W1 + (size_t)l * HD * HD, b1 + l * HD,
                                     T_NONE, T_T, NN, HD, HD, HD);
        // o = t @ W2 + b2
        sgemm<false><<<GEMM_G, TB>>>(nullptr, T_T,
                                     W2 + (size_t)l * HD * HD, b2 + l * HD,
                                     T_NONE, T_O, NN, HD, HD, HD);
        // BatchNorm (batch stats) + ReLU -> x
        bn_zero<<<1, 128>>>();
        bn_reduce<<<256, 128>>>();
        bn_final<<<1, 128>>>(gamma + l * HD, beta + l * HD);
        norm_relu<<<WARP_BLK, TB>>>();
    }

    // ---- GAT ----
    sgemm<false><<<GEMM_G4, TB>>>(nullptr, T_X, Wg, nullptr, T_NONE, T_HF,
                                  NN, HD, 512, 512);
    gat_node1<<<WARP_BLK, TB>>>(att_src, att_dst);
    gat_edge1<<<EDGE_BLK, TB>>>(ei);
    gat_node2<<<NODE_BLK, TB>>>();
    gat_edge2<<<EDGE_BLK, TB>>>(ei);
    gat_node3<<<WARP_BLK, TB>>>(bg);

    // ---- pool + fc ----
    pool_kernel<<<NG, 128>>>(batch);
    final_kernel<<<(NG * NOUT + TB - 1) / TB, TB>>>(Wfc, bfc, out);
}

// round 5
// speedup vs baseline: 1.0647x; 1.0647x over previous
#include <cuda_runtime.h>
#include <cuda_bf16.h>

// ---------------- problem constants ----------------
constexpr int NN   = 50000;   // nodes
constexpr int NE   = 512000;  // edges
constexpr int HD   = 128;     // hidden
constexpr int EDIM = 32;      // edge dim
constexpr int NL   = 10;      // GINE layers
constexpr int NG   = 64;      // graphs
constexpr int NOUT = 10;
constexpr float EPSF  = 1e-5f;
constexpr float SLOPE = 0.2f;

typedef unsigned long long u64;
typedef unsigned int u32;

// ---------------- generic helpers ----------------
__device__ __forceinline__ float lrelu(float v) { return v < 0.f ? SLOPE * v : v; }
__device__ __forceinline__ u32 ford(float f) {
    u32 u = __float_as_uint(f);
    return (u & 0x80000000u) ? ~u : (u | 0x80000000u);
}
__device__ __forceinline__ float funord(u32 u) {
    return __uint_as_float((u & 0x80000000u) ? (u ^ 0x80000000u) : ~u);
}
__device__ __forceinline__ u32 smem_u32(const void* p) {
    u32 a; asm("{ .reg .u64 t; cvta.to.shared.u64 t, %1; cvt.u32.u64 %0, t; }" : "=r"(a) : "l"(p));
    return a;
}

// ---------------- mma.sync helpers (plain sm_100-safe PTX) ----------------
__device__ __forceinline__ void ldsm_x4(u32* r, u32 addr) {
    asm volatile("ldmatrix.sync.aligned.m8n8.x4.shared.b16 {%0,%1,%2,%3}, [%4];"
                 : "=r"(r[0]), "=r"(r[1]), "=r"(r[2]), "=r"(r[3]) : "r"(addr));
}
__device__ __forceinline__ void ldsm_x2t(u32* r, u32 addr) {
    asm volatile("ldmatrix.sync.aligned.m8n8.x2.trans.shared.b16 {%0,%1}, [%2];"
                 : "=r"(r[0]), "=r"(r[1]) : "r"(addr));
}
__device__ __forceinline__ void mma16816(float* c, const u32* a, const u32* b) {
    asm volatile("mma.sync.aligned.m16n8k16.row.col.f32.bf16.bf16.f32 "
                 "{%0,%1,%2,%3}, {%4,%5,%6,%7}, {%8,%9}, {%0,%1,%2,%3};"
                 : "+f"(c[0]), "+f"(c[1]), "+f"(c[2]), "+f"(c[3])
                 : "r"(a[0]), "r"(a[1]), "r"(a[2]), "r"(a[3]), "r"(b[0]), "r"(b[1]));
}

// ---------------- device scratch (no allocs allowed) ----------------
__device__ __align__(16) float g_hn[NN * HD];
__device__ __align__(16) float g_agg[NN * HD];
__device__ __align__(16) float g_t[NN * HD];
__device__ __align__(16) float g_o[NN * HD];
__device__ __align__(16) float g_x[NN * HD];
__device__ __align__(16) float g_hfeat[NN * 4 * HD];   // GAT features [N,4,128]
__device__ __align__(16) float g_eagg[NN * 128];       // K-padded to 128 (cols 32.. = 0)
__device__           float g_degf[NN];
__device__           int   g_deg[NN];
__device__           int   g_rowptr[NN + 1];
__device__           int   g_cursor[NN];
__device__           int   g_csrc[NE];
__device__           int   g_ceid[NE];
__device__ __align__(16) float g_as[NN * 4];
__device__ __align__(16) float g_ad[NN * 4];
__device__ __align__(16) u32   g_amax[NN * 4];
__device__ __align__(16) float g_den[NN * 4];
__device__ __align__(16) float g_bnsum[HD];
__device__ __align__(16) float g_bnsq[HD];
__device__ __align__(16) float g_scale[HD];
__device__ __align__(16) float g_shift[HD];
__device__ __align__(16) float g_pool[NG * HD];

// Prepped weights: 44 matrices, each hi (34816B) + lo (34816B), row-major [K][136] bf16.
// m: 0..9 Wn[l], 10..19 W1[l], 20..29 W2[l], 30..39 We[l] (K-padded), 40..43 Wg col blocks
constexpr int NMAT = 44;
constexpr int WPAD = 136;                       // padded row length (elements)
constexpr int WHALF = 128 * WPAD * 2;           // 34816 bytes per half
constexpr int WMAT_BYTES = 2 * WHALF;           // 69632 bytes per matrix
__device__ __align__(16) char g_wb[(size_t)NMAT * WMAT_BYTES];

// Device-side buffer dispatch (keeps kernel_launch to pure kernel launches)
enum BufTag { T_NONE = 0, T_HN, T_AGG, T_T, T_O, T_X, T_HF, T_EA, T_DEGF };
__device__ __forceinline__ float* bufptr(int t) {
    switch (t) {
        case T_HN:   return g_hn;
        case T_AGG:  return g_agg;
        case T_T:    return g_t;
        case T_O:    return g_o;
        case T_X:    return g_x;
        case T_HF:   return g_hfeat;
        case T_EA:   return g_eagg;
        case T_DEGF: return g_degf;
        default:     return nullptr;
    }
}

// ---------------- weight prep: fp32 [K,N] -> bf16 hi/lo, padded row-major ----------------
__global__ void prep_weights(const float* __restrict__ Wn, const float* __restrict__ W1,
                             const float* __restrict__ W2, const float* __restrict__ We,
                             const float* __restrict__ Wg) {
    int m = blockIdx.x;
    char* dst = g_wb + (size_t)m * WMAT_BYTES;
    for (int idx = threadIdx.x; idx < 16384; idx += blockDim.x) {
        int k = idx >> 7, n = idx & 127;
        float v;
        if (m < 10)       v = Wn[(size_t)m * 16384 + k * 128 + n];
        else if (m < 20)  v = W1[(size_t)(m - 10) * 16384 + k * 128 + n];
        else if (m < 30)  v = W2[(size_t)(m - 20) * 16384 + k * 128 + n];
        else if (m < 40)  v = (k < EDIM) ? We[(size_t)(m - 30) * EDIM * 128 + k * 128 + n] : 0.f;
        else              v = Wg[(size_t)k * 512 + (m - 40) * 128 + n];
        __nv_bfloat16 h = __float2bfloat16(v);
        __nv_bfloat16 l = __float2bfloat16(v - __bfloat162float(h));
        ((__nv_bfloat16*)dst)[k * WPAD + n]             = h;
        ((__nv_bfloat16*)(dst + WHALF))[k * WPAD + n]   = l;
    }
}

// ---------------- tensor-core GEMM via mma.sync: C[M,128] = A[M,128] @ W ----------------
// bf16x3 emulation of fp32: AhWh + AhWl + AlWh, fp32 accumulate.
// 256 threads, one 128x128 tile per CTA, 8 warps as 2(M)x4(N) of 64x32 warp tiles.
constexpr int SM_AH = 0;
constexpr int SM_AL = WHALF;          // 34816
constexpr int SM_BH = 2 * WHALF;      // 69632
constexpr int SM_BL = 3 * WHALF;      // 104448
constexpr int SM_TOT = 4 * WHALF;     // 139264

template<bool RELU>
__global__ void __launch_bounds__(256, 1)
mma_gemm(const float* __restrict__ Aext, int Atag, int wmat,
         const float* __restrict__ bias, int rstag, int Ctag, int ldc)
{
    extern __shared__ __align__(16) char smem[];
    u32 sb = smem_u32(smem);
    int tid = threadIdx.x, wid = tid >> 5, lane = tid & 31;
    int row0 = blockIdx.x * 128;
    int colb = blockIdx.y * 128;
    wmat += blockIdx.y;

    const float* A = Aext ? Aext : bufptr(Atag);
    const float* rowscale = rstag ? bufptr(rstag) : nullptr;
    float* C = bufptr(Ctag);

    // copy prepped weights (hi+lo, 69632B) into SMEM (contiguous)
    {
        const uint4* src = (const uint4*)(g_wb + (size_t)wmat * WMAT_BYTES);
        uint4* dst = (uint4*)(smem + SM_BH);
#pragma unroll
        for (int i = 0; i < 17; i++) dst[i * 256 + tid] = src[i * 256 + tid];
    }

    // load A tile (fp32), split to bf16 hi/lo, padded row-major
    {
        int r = tid >> 1, cb = (tid & 1) * 64;
        bool valid = (row0 + r) < NN;
        const float2* arow = (const float2*)(A + (size_t)(row0 + r) * 128 + cb);
        u32* AH = (u32*)(smem + SM_AH) + (r * WPAD + cb) / 2;
        u32* AL = (u32*)(smem + SM_AL) + (r * WPAD + cb) / 2;
#pragma unroll 8
        for (int i = 0; i < 32; i++) {
            float2 v = valid ? arow[i] : make_float2(0.f, 0.f);
            __nv_bfloat16 hx = __float2bfloat16(v.x), hy = __float2bfloat16(v.y);
            __nv_bfloat16 lx = __float2bfloat16(v.x - __bfloat162float(hx));
            __nv_bfloat16 ly = __float2bfloat16(v.y - __bfloat162float(hy));
            AH[i] = (u32)__bfloat16_as_ushort(hx) | ((u32)__bfloat16_as_ushort(hy) << 16);
            AL[i] = (u32)__bfloat16_as_ushort(lx) | ((u32)__bfloat16_as_ushort(ly) << 16);
        }
    }
    __syncthreads();

    int wm = wid >> 2;        // 0..1 : 64-row warp tile
    int wn = wid & 3;         // 0..3 : 32-col warp tile

    float acc[4][4][4];
#pragma unroll
    for (int i = 0; i < 4; i++)
#pragma unroll
        for (int j = 0; j < 4; j++)
#pragma unroll
            for (int q = 0; q < 4; q++) acc[i][j][q] = 0.f;

    const u32 aoff[3] = { SM_AH, SM_AH, SM_AL };
    const u32 boff[3] = { SM_BH, SM_BL, SM_BH };

#pragma unroll
    for (int p = 0; p < 3; p++) {
        // A: lane -> row (lane&15) within 16-row subtile, col half (lane>>4)*8
        u32 sa0 = sb + aoff[p] + ((wm * 64 + (lane & 15)) * WPAD + (lane >> 4) * 8) * 2;
        // B: lane -> k row (lane&15), col base wn*32
        u32 sb0 = sb + boff[p] + ((lane & 15) * WPAD + wn * 32) * 2;
#pragma unroll
        for (int k = 0; k < 8; k++) {
            u32 af[4][4];
#pragma unroll
            for (int i = 0; i < 4; i++)
                ldsm_x4(af[i], sa0 + i * 16 * (WPAD * 2) + k * 32);
            u32 bf[4][2];
#pragma unroll
            for (int j = 0; j < 4; j++)
                ldsm_x2t(bf[j], sb0 + k * 16 * (WPAD * 2) + j * 16);
#pragma unroll
            for (int i = 0; i < 4; i++)
#pragma unroll
                for (int j = 0; j < 4; j++)
                    mma16816(acc[i][j], af[i], bf[j]);
        }
    }

    // epilogue: lane owns rows (l>>2, +8), cols (l&3)*2 pair per 16x8 fragment
#pragma unroll
    for (int i = 0; i < 4; i++) {
        int ra = row0 + wm * 64 + i * 16 + (lane >> 2);
#pragma unroll
        for (int half = 0; half < 2; half++) {
            int row = ra + half * 8;
            if (row < NN) {
                float rs = rowscale ? rowscale[row] : 1.f;
#pragma unroll
                for (int j = 0; j < 4; j++) {
                    int cc = wn * 32 + j * 8 + (lane & 3) * 2;
                    float b0 = 0.f, b1 = 0.f;
                    if (bias) { b0 = bias[cc]; b1 = bias[cc + 1]; }
                    float v0 = acc[i][j][half * 2 + 0] + rs * b0;
                    float v1 = acc[i][j][half * 2 + 1] + rs * b1;
                    if (RELU) { v0 = fmaxf(v0, 0.f); v1 = fmaxf(v1, 0.f); }
                    *(float2*)&C[(size_t)row * ldc + colb + cc] = make_float2(v0, v1);
                }
            }
        }
    }
}

// ---------------- CSR build ----------------
__global__ void zero_deg() {
    int i = blockIdx.x * blockDim.x + threadIdx.x;
    if (i < NN) g_deg[i] = 0;
}
__global__ void hist_kernel(const int* __restrict__ ei) {
    int e = blockIdx.x * blockDim.x + threadIdx.x;
    if (e < NE) atomicAdd(&g_deg[ei[NE + e]], 1);
}
__global__ void scan_kernel() {
    __shared__ int sh[1024];
    __shared__ int carry;
    int tid = threadIdx.x;
    if (tid == 0) carry = 0;
    __syncthreads();
    for (int base = 0; base < NN; base += 1024) {
        int i = base + tid;
        int v = (i < NN) ? g_deg[i] : 0;
        sh[tid] = v;
        __syncthreads();
        for (int off = 1; off < 1024; off <<= 1) {
            int t = (tid >= off) ? sh[tid - off] : 0;
            __syncthreads();
            sh[tid] += t;
            __syncthreads();
        }
        int incl = sh[tid];
        int excl = incl - v + carry;
        if (i < NN) {
            g_rowptr[i] = excl;
            g_cursor[i] = excl;
            g_degf[i]   = (float)v;
        }
        __syncthreads();
        if (tid == 1023) carry += incl;
        __syncthreads();
    }
    if (tid == 0) g_rowptr[NN] = carry;
}
__global__ void scatter_kernel(const int* __restrict__ ei) {
    int e = blockIdx.x * blockDim.x + threadIdx.x;
    if (e >= NE) return;
    int s = ei[e], d = ei[NE + e];
    int p = atomicAdd(&g_cursor[d], 1);
    g_csrc[p] = s;
    g_ceid[p] = e;
}
// Eagg[n,0:32] = sum over in-edges of edge_attr[e,:]; cols 32..127 zeroed (K-pad)
__global__ void eagg_kernel(const float* __restrict__ edge_attr) {
    int w = (blockIdx.x * blockDim.x + threadIdx.x) >> 5;
    if (w >= NN) return;
    int lane = threadIdx.x & 31;
    float acc = 0.f;
    int p0 = g_rowptr[w], p1 = g_rowptr[w + 1];
    for (int p = p0; p < p1; p++) {
        int e = g_ceid[p];
        acc += edge_attr[e * EDIM + lane];
    }
    g_eagg[w * 128 + lane] = acc;
    g_eagg[w * 128 + 32 + lane] = 0.f;
    g_eagg[w * 128 + 64 + lane] = 0.f;
    g_eagg[w * 128 + 96 + lane] = 0.f;
}

// ---------------- GINE aggregation: agg[n] += sum hn[src] (CSR, atomic-free) ----------------
__global__ void gine_aggregate() {
    int w = (blockIdx.x * blockDim.x + threadIdx.x) >> 5;
    if (w >= NN) return;
    int lane = threadIdx.x & 31;
    float4 acc = *(const float4*)&g_agg[w * HD + lane * 4];
    int p0 = g_rowptr[w], p1 = g_rowptr[w + 1];
    for (int p = p0; p < p1; p++) {
        int s = g_csrc[p];
        const float4 v = *(const float4*)&g_hn[s * HD + lane * 4];
        acc.x += v.x; acc.y += v.y; acc.z += v.z; acc.w += v.w;
    }
    *(float4*)&g_agg[w * HD + lane * 4] = acc;
}

// ---------------- BatchNorm ----------------
__global__ void bn_zero() {
    int c = threadIdx.x;
    if (c < HD) { g_bnsum[c] = 0.f; g_bnsq[c] = 0.f; }
}
__global__ void bn_reduce() {
    int c = threadIdx.x;
    float s = 0.f, q = 0.f;
    for (int r = blockIdx.x; r < NN; r += gridDim.x) {
        float v = g_o[r * HD + c];
        s += v; q += v * v;
    }
    atomicAdd(&g_bnsum[c], s);
    atomicAdd(&g_bnsq[c], q);
}
__global__ void bn_final(const float* __restrict__ gamma, const float* __restrict__ beta) {
    int c = threadIdx.x;
    if (c >= HD) return;
    float mu  = g_bnsum[c] / (float)NN;
    float var = g_bnsq[c] / (float)NN - mu * mu;
    float sc  = gamma[c] * rsqrtf(var + EPSF);
    g_scale[c] = sc;
    g_shift[c] = beta[c] - mu * sc;
}
__global__ void norm_relu() {
    int i = blockIdx.x * blockDim.x + threadIdx.x;  // over N*32 float4s
    if (i >= NN * 32) return;
    float4 v = ((const float4*)g_o)[i];
    int c = (i & 31) * 4;
    float4 sc = *(const float4*)&g_scale[c];
    float4 sh = *(const float4*)&g_shift[c];
    v.x = fmaxf(v.x * sc.x + sh.x, 0.f);
    v.y = fmaxf(v.y * sc.y + sh.y, 0.f);
    v.z = fmaxf(v.z * sc.z + sh.z, 0.f);
    v.w = fmaxf(v.w * sc.w + sh.w, 0.f);
    ((float4*)g_x)[i] = v;
}

// ---------------- GAT ----------------
__global__ void gat_node1(const float* __restrict__ att_src, const float* __restrict__ att_dst) {
    int n = (blockIdx.x * blockDim.x + threadIdx.x) >> 5;
    if (n >= NN) return;
    int lane = threadIdx.x & 31;
    float s[4], d[4];
#pragma unroll
    for (int h = 0; h < 4; h++) {
        float4 hv = *(const float4*)&g_hfeat[n * 512 + h * 128 + lane * 4];
        float4 a1 = *(const float4*)&att_src[h * 128 + lane * 4];
        float4 a2 = *(const float4*)&att_dst[h * 128 + lane * 4];
        float ps = hv.x * a1.x + hv.y * a1.y + hv.z * a1.z + hv.w * a1.w;
        float pd = hv.x * a2.x + hv.y * a2.y + hv.z * a2.z + hv.w * a2.w;
#pragma unroll
        for (int off = 16; off > 0; off >>= 1) {
            ps += __shfl_xor_sync(0xffffffffu, ps, off);
            pd += __shfl_xor_sync(0xffffffffu, pd, off);
        }
        s[h] = ps; d[h] = pd;
    }
    if (lane == 0) {
#pragma unroll
        for (int h = 0; h < 4; h++) {
            g_as[n * 4 + h] = s[h];
            g_ad[n * 4 + h] = d[h];
            g_amax[n * 4 + h] = ford(lrelu(s[h] + d[h]));   // self-loop seeds the max
        }
    }
}
__global__ void gat_edge1(const int* __restrict__ ei) {
    int e = blockIdx.x * blockDim.x + threadIdx.x;
    if (e >= NE) return;
    int s = ei[e], d = ei[NE + e];
    float4 a = *(const float4*)&g_as[s * 4];
    float4 b = *(const float4*)&g_ad[d * 4];
    atomicMax(&g_amax[d * 4 + 0], ford(lrelu(a.x + b.x)));
    atomicMax(&g_amax[d * 4 + 1], ford(lrelu(a.y + b.y)));
    atomicMax(&g_amax[d * 4 + 2], ford(lrelu(a.z + b.z)));
    atomicMax(&g_amax[d * 4 + 3], ford(lrelu(a.w + b.w)));
}
__global__ void gat_node2() {  // denom init = self-loop term
    int n = blockIdx.x * blockDim.x + threadIdx.x;
    if (n >= NN) return;
    float4 a = *(const float4*)&g_as[n * 4];
    float4 b = *(const float4*)&g_ad[n * 4];
    uint4 mu = *(const uint4*)&g_amax[n * 4];
    float4 den;
    den.x = __expf(lrelu(a.x + b.x) - funord(mu.x));
    den.y = __expf(lrelu(a.y + b.y) - funord(mu.y));
    den.z = __expf(lrelu(a.z + b.z) - funord(mu.z));
    den.w = __expf(lrelu(a.w + b.w) - funord(mu.w));
    *(float4*)&g_den[n * 4] = den;
}
__global__ void gat_edge2(const int* __restrict__ ei) {
    int e = blockIdx.x * blockDim.x + threadIdx.x;
    if (e >= NE) return;
    int s = ei[e], d = ei[NE + e];
    float4 a = *(const float4*)&g_as[s * 4];
    float4 b = *(const float4*)&g_ad[d * 4];
    uint4 mu = *(const uint4*)&g_amax[d * 4];
    atomicAdd(&g_den[d * 4 + 0], __expf(lrelu(a.x + b.x) - funord(mu.x)));
    atomicAdd(&g_den[d * 4 + 1], __expf(lrelu(a.y + b.y) - funord(mu.y)));
    atomicAdd(&g_den[d * 4 + 2], __expf(lrelu(a.z + b.z) - funord(mu.z)));
    atomicAdd(&g_den[d * 4 + 3], __expf(lrelu(a.w + b.w) - funord(mu.w)));
}
__global__ void gat_node3(const float* __restrict__ bg) {
    int n = (blockIdx.x * blockDim.x + threadIdx.x) >> 5;
    if (n >= NN) return;
    int lane = threadIdx.x & 31;
    float4 adn = *(const float4*)&g_ad[n * 4];
    float4 asn = *(const float4*)&g_as[n * 4];
    uint4 mu = *(const uint4*)&g_amax[n * 4];
    float m0 = funord(mu.x), m1 = funord(mu.y), m2 = funord(mu.z), m3 = funord(mu.w);
    float4 den = *(const float4*)&g_den[n * 4];
    float i0 = 1.f / den.x, i1 = 1.f / den.y, i2 = 1.f / den.z, i3 = 1.f / den.w;

    float w0 = __expf(lrelu(asn.x + adn.x) - m0) * i0;
    float w1 = __expf(lrelu(asn.y + adn.y) - m1) * i1;
    float w2 = __expf(lrelu(asn.z + adn.z) - m2) * i2;
    float w3 = __expf(lrelu(asn.w + adn.w) - m3) * i3;

    int base = n * 512 + lane * 4;
    float4 h0 = *(const float4*)&g_hfeat[base];
    float4 h1 = *(const float4*)&g_hfeat[base + 128];
    float4 h2 = *(const float4*)&g_hfeat[base + 256];
    float4 h3 = *(const float4*)&g_hfeat[base + 384];
    float4 A0 = { w0 * h0.x, w0 * h0.y, w0 * h0.z, w0 * h0.w };
    float4 A1 = { w1 * h1.x, w1 * h1.y, w1 * h1.z, w1 * h1.w };
    float4 A2 = { w2 * h2.x, w2 * h2.y, w2 * h2.z, w2 * h2.w };
    float4 A3 = { w3 * h3.x, w3 * h3.y, w3 * h3.z, w3 * h3.w };

    int p0 = g_rowptr[n], p1 = g_rowptr[n + 1];
    for (int p = p0; p < p1; p++) {
        int s = g_csrc[p];
        float4 ass = *(const float4*)&g_as[s * 4];
        float e0 = __expf(lrelu(ass.x + adn.x) - m0) * i0;
        float e1 = __expf(lrelu(ass.y + adn.y) - m1) * i1;
        float e2 = __expf(lrelu(ass.z + adn.z) - m2) * i2;
        float e3 = __expf(lrelu(ass.w + adn.w) - m3) * i3;
        int sb = s * 512 + lane * 4;
        float4 v0 = *(const float4*)&g_hfeat[sb];
        float4 v1 = *(const float4*)&g_hfeat[sb + 128];
        float4 v2 = *(const float4*)&g_hfeat[sb + 256];
        float4 v3 = *(const float4*)&g_hfeat[sb + 384];
        A0.x += e0 * v0.x; A0.y += e0 * v0.y; A0.z += e0 * v0.z; A0.w += e0 * v0.w;
        A1.x += e1 * v1.x; A1.y += e1 * v1.y; A1.z += e1 * v1.z; A1.w += e1 * v1.w;
        A2.x += e2 * v2.x; A2.y += e2 * v2.y; A2.z += e2 * v2.z; A2.w += e2 * v2.w;
        A3.x += e3 * v3.x; A3.y += e3 * v3.y; A3.z += e3 * v3.z; A3.w += e3 * v3.w;
    }
    float4 bg4 = *(const float4*)&bg[lane * 4];
    float4 o4;
    o4.x = (A0.x + A1.x + A2.x + A3.x) * 0.25f + bg4.x;
    o4.y = (A0.y + A1.y + A2.y + A3.y) * 0.25f + bg4.y;
    o4.z = (A0.z + A1.z + A2.z + A3.z) * 0.25f + bg4.z;
    o4.w = (A0.w + A1.w + A2.w + A3.w) * 0.25f + bg4.w;
    *(float4*)&g_x[n * HD + lane * 4] = o4;
}

// ---------------- pooling + fc (batch sorted -> per-graph range, no atomics) ----------------
__device__ __forceinline__ int lbound(const int* a, int n, int key) {
    int lo = 0, hi = n;
    while (lo < hi) { int mid = (lo + hi) >> 1; if (a[mid] < key) lo = mid + 1; else hi = mid; }
    return lo;
}
__global__ void pool_kernel(const int* __restrict__ batch) {
    int g = blockIdx.x;
    int c = threadIdx.x;   // 128 threads
    __shared__ int slo, shi;
    if (c == 0) { slo = lbound(batch, NN, g); shi = lbound(batch, NN, g + 1); }
    __syncthreads();
    int lo = slo, hi = shi;
    float a0 = 0.f, a1 = 0.f, a2 = 0.f, a3 = 0.f;
    int n = lo;
    for (; n + 4 <= hi; n += 4) {
        a0 += g_x[n * HD + c];
        a1 += g_x[(n + 1) * HD + c];
        a2 += g_x[(n + 2) * HD + c];
        a3 += g_x[(n + 3) * HD + c];
    }
    for (; n < hi; n++) a0 += g_x[n * HD + c];
    float s = (a0 + a1) + (a2 + a3);
    g_pool[g * HD + c] = s / fmaxf((float)(hi - lo), 1.f);
}
__global__ void final_kernel(const float* __restrict__ Wfc, const float* __restrict__ bfc,
                             float* __restrict__ out) {
    int idx = blockIdx.x * blockDim.x + threadIdx.x;
    if (idx >= NG * NOUT) return;
    int g = idx / NOUT, o = idx % NOUT;
    float s = bfc[o];
#pragma unroll 8
    for (int k = 0; k < HD; k++) s += g_pool[g * HD + k] * Wfc[k * NOUT + o];
    out[idx] = s;
}

// ---------------- driver (kernel launches only — graph-capture safe) ----------------
extern "C" void kernel_launch(void* const* d_in, const int* in_sizes, int n_in,
                              void* d_out, int out_size) {
    const float* x_in      = (const float*)d_in[0];
    const float* edge_attr = (const float*)d_in[1];
    const int*   ei        = (const int*)d_in[2];
    const int*   batch     = (const int*)d_in[3];
    const float* Wn   = (const float*)d_in[4];
    const float* bn_b = (const float*)d_in[5];
    const float* We   = (const float*)d_in[6];
    const float* be_b = (const float*)d_in[7];
    const float* W1   = (const float*)d_in[8];
    const float* b1   = (const float*)d_in[9];
    const float* W2   = (const float*)d_in[10];
    const float* b2   = (const float*)d_in[11];
    const float* gamma= (const float*)d_in[12];
    const float* beta = (const float*)d_in[13];
    const float* Wg   = (const float*)d_in[14];
    const float* att_src = (const float*)d_in[15];
    const float* att_dst = (const float*)d_in[16];
    const float* bg   = (const float*)d_in[17];
    const float* Wfc  = (const float*)d_in[18];
    const float* bfc  = (const float*)d_in[19];
    float* out = (float*)d_out;

    // Opt into >48KB dynamic SMEM for the GEMM (host attr, not a graph node)
    cudaFuncSetAttribute(mma_gemm<false>, cudaFuncAttributeMaxDynamicSharedMemorySize, SM_TOT);
    cudaFuncSetAttribute(mma_gemm<true>,  cudaFuncAttributeMaxDynamicSharedMemorySize, SM_TOT);

    const int TB = 256;
    const int NODE_BLK = (NN + TB - 1) / TB;                 // 196
    const int EDGE_BLK = (NE + TB - 1) / TB;                 // 2000
    const int WARP_BLK = (NN * 32 + TB - 1) / TB;            // 6250
    const dim3 GEMM_G(391, 1);
    const dim3 GEMM_G4(391, 4);

    // ---- graph structure + weight prep (layer-invariant) ----
    zero_deg<<<NODE_BLK, TB>>>();
    hist_kernel<<<EDGE_BLK, TB>>>(ei);
    prep_weights<<<NMAT, 256>>>(Wn, W1, W2, We, Wg);
    scan_kernel<<<1, 1024>>>();
    scatter_kernel<<<EDGE_BLK, TB>>>(ei);
    eagg_kernel<<<WARP_BLK, TB>>>(edge_attr);

    // ---- 10 GINE layers ----
    for (int l = 0; l < NL; l++) {
        // hn = x @ Wn + bn_b
        mma_gemm<false><<<GEMM_G, 256, SM_TOT>>>((l == 0) ? x_in : nullptr, T_X, l,
                                                 bn_b + l * HD, T_NONE, T_HN, HD);
        // agg = Eagg @ We + deg*be_b   (edge-encoder term, algebraically hoisted)
        mma_gemm<false><<<GEMM_G, 256, SM_TOT>>>(nullptr, T_EA, 30 + l,
                                                 be_b + l * HD, T_DEGF, T_AGG, HD);
        // agg += sum_{in-edges} hn[src]
        gine_aggregate<<<WARP_BLK, TB>>>();
        // t = relu(agg @ W1 + b1)
        mma_gemm<true ><<<GEMM_G, 256, SM_TOT>>>(nullptr, T_AGG, 10 + l,
                                                 b1 + l * HD, T_NONE, T_T, HD);
        // o = t @ W2 + b2
        mma_gemm<false><<<GEMM_G, 256, SM_TOT>>>(nullptr, T_T, 20 + l,
                                                 b2 + l * HD, T_NONE, T_O, HD);
        // BatchNorm (batch stats) + ReLU -> x
        bn_zero<<<1, 128>>>();
        bn_reduce<<<256, 128>>>();
        bn_final<<<1, 128>>>(gamma + l * HD, beta + l * HD);
        norm_relu<<<WARP_BLK, TB>>>();
    }

    // ---- GAT ----
    mma_gemm<false><<<GEMM_G4, 256, SM_TOT>>>(nullptr, T_X, 40, nullptr, T_NONE, T_HF, 512);
    gat_node1<<<WARP_BLK, TB>>>(att_src, att_dst);
    gat_edge1<<<EDGE_BLK, TB>>>(ei);
    gat_node2<<<NODE_BLK, TB>>>();
    gat_edge2<<<EDGE_BLK, TB>>>(ei);
    gat_node3<<<WARP_BLK, TB>>>(bg);

    // ---- pool + fc ----
    pool_kernel<<<NG, 128>>>(batch);
    final_kernel<<<(NG * NOUT + TB - 1) / TB, TB>>>(Wfc, bfc, out);
}

// round 6
// speedup vs baseline: 1.1923x; 1.1198x over previous
#include <cuda_runtime.h>
#include <cuda_bf16.h>

// ---------------- problem constants ----------------
constexpr int NN   = 50000;   // nodes
constexpr int NE   = 512000;  // edges
constexpr int HD   = 128;     // hidden
constexpr int EDIM = 32;      // edge dim
constexpr int NL   = 10;      // GINE layers
constexpr int NG   = 64;      // graphs
constexpr int NOUT = 10;
constexpr float EPSF  = 1e-5f;
constexpr float SLOPE = 0.2f;

typedef unsigned long long u64;
typedef unsigned int u32;

// ---------------- generic helpers ----------------
__device__ __forceinline__ float lrelu(float v) { return v < 0.f ? SLOPE * v : v; }
__device__ __forceinline__ u32 smem_u32(const void* p) {
    u32 a; asm("{ .reg .u64 t; cvta.to.shared.u64 t, %1; cvt.u32.u64 %0, t; }" : "=r"(a) : "l"(p));
    return a;
}
__device__ __forceinline__ u32 pack_bf2(float a, float b) {
    return (u32)__bfloat16_as_ushort(__float2bfloat16(a)) |
           ((u32)__bfloat16_as_ushort(__float2bfloat16(b)) << 16);
}
__device__ __forceinline__ float bf_lo(u32 v) {
    return __bfloat162float(__ushort_as_bfloat16((unsigned short)(v & 0xffff)));
}
__device__ __forceinline__ float bf_hi(u32 v) {
    return __bfloat162float(__ushort_as_bfloat16((unsigned short)(v >> 16)));
}

// ---------------- mma.sync helpers (plain sm_100-safe PTX) ----------------
__device__ __forceinline__ void ldsm_x4(u32* r, u32 addr) {
    asm volatile("ldmatrix.sync.aligned.m8n8.x4.shared.b16 {%0,%1,%2,%3}, [%4];"
                 : "=r"(r[0]), "=r"(r[1]), "=r"(r[2]), "=r"(r[3]) : "r"(addr));
}
__device__ __forceinline__ void ldsm_x2t(u32* r, u32 addr) {
    asm volatile("ldmatrix.sync.aligned.m8n8.x2.trans.shared.b16 {%0,%1}, [%2];"
                 : "=r"(r[0]), "=r"(r[1]) : "r"(addr));
}
__device__ __forceinline__ void mma16816(float* c, const u32* a, const u32* b) {
    asm volatile("mma.sync.aligned.m16n8k16.row.col.f32.bf16.bf16.f32 "
                 "{%0,%1,%2,%3}, {%4,%5,%6,%7}, {%8,%9}, {%0,%1,%2,%3};"
                 : "+f"(c[0]), "+f"(c[1]), "+f"(c[2]), "+f"(c[3])
                 : "r"(a[0]), "r"(a[1]), "r"(a[2]), "r"(a[3]), "r"(b[0]), "r"(b[1]));
}
__device__ __forceinline__ void cp_async16(u32 dst, const void* src) {
    asm volatile("cp.async.cg.shared.global [%0], [%1], 16;" :: "r"(dst), "l"(src));
}
__device__ __forceinline__ void cp_async_wait_all() {
    asm volatile("cp.async.commit_group;");
    asm volatile("cp.async.wait_group 0;" ::: "memory");
}

// ---------------- device scratch (no allocs allowed) ----------------
__device__ __align__(16) u32   g_hnb[NN * 64];         // hn in packed bf16x2
__device__ __align__(16) float g_agg[NN * HD];
__device__ __align__(16) float g_t[NN * HD];
__device__ __align__(16) float g_o[NN * HD];
__device__ __align__(16) float g_x[NN * HD];
__device__ __align__(16) float g_hfeat[NN * 4 * HD];   // GAT features [N,4,128]
__device__ __align__(16) float g_eagg[NN * 128];       // K-padded to 128 (cols 32.. = 0)
__device__           float g_degf[NN];
__device__           int   g_deg[NN];
__device__           int   g_rowptr[NN + 1];
__device__           int   g_cursor[NN];
__device__           int   g_csrc[NE];
__device__           int   g_ceid[NE];
__device__           int   g_bsum[64];
__device__           int   g_boff[64];
__device__ __align__(16) float g_as[NN * 4];
__device__ __align__(16) float g_ad[NN * 4];
__device__ __align__(16) float g_bnsum[HD];
__device__ __align__(16) float g_bnsq[HD];
__device__ __align__(16) float g_scale[HD];
__device__ __align__(16) float g_shift[HD];
__device__ __align__(16) float g_pool[NG * HD];

// Prepped weights: 44 matrices, each hi (34816B) + lo (34816B), row-major [K][136] bf16.
// m: 0..9 Wn[l], 10..19 W1[l], 20..29 W2[l], 30..39 We[l] (K-padded), 40..43 Wg col blocks
constexpr int NMAT = 44;
constexpr int WPAD = 136;
constexpr int WHALF = 128 * WPAD * 2;           // 34816 bytes per half
constexpr int WMAT_BYTES = 2 * WHALF;           // 69632 bytes per matrix
__device__ __align__(16) char g_wb[(size_t)NMAT * WMAT_BYTES];

enum BufTag { T_NONE = 0, T_AGG, T_T, T_O, T_HF, T_EA, T_DEGF, T_HN };
__device__ __forceinline__ float* bufptr(int t) {
    switch (t) {
        case T_AGG:  return g_agg;
        case T_T:    return g_t;
        case T_O:    return g_o;
        case T_HF:   return g_hfeat;
        case T_EA:   return g_eagg;
        case T_DEGF: return g_degf;
        default:     return nullptr;
    }
}

// ---------------- weight prep: fp32 [K,N] -> bf16 hi/lo, padded row-major ----------------
__global__ void prep_weights(const float* __restrict__ Wn, const float* __restrict__ W1,
                             const float* __restrict__ W2, const float* __restrict__ We,
                             const float* __restrict__ Wg) {
    int m = blockIdx.x;
    char* dst = g_wb + (size_t)m * WMAT_BYTES;
    for (int idx = threadIdx.x; idx < 16384; idx += blockDim.x) {
        int k = idx >> 7, n = idx & 127;
        float v;
        if (m < 10)       v = Wn[(size_t)m * 16384 + k * 128 + n];
        else if (m < 20)  v = W1[(size_t)(m - 10) * 16384 + k * 128 + n];
        else if (m < 30)  v = W2[(size_t)(m - 20) * 16384 + k * 128 + n];
        else if (m < 40)  v = (k < EDIM) ? We[(size_t)(m - 30) * EDIM * 128 + k * 128 + n] : 0.f;
        else              v = Wg[(size_t)k * 512 + (m - 40) * 128 + n];
        __nv_bfloat16 h = __float2bfloat16(v);
        __nv_bfloat16 l = __float2bfloat16(v - __bfloat162float(h));
        ((__nv_bfloat16*)dst)[k * WPAD + n]           = h;
        ((__nv_bfloat16*)(dst + WHALF))[k * WPAD + n] = l;
    }
}

// ---------------- tensor-core GEMM via mma.sync ----------------
// bf16x3 emulation of fp32: AhWh + AhWl + AlWh, fp32 accumulate.
// 256 threads, one 128x128 tile per CTA, 8 warps as 2(M)x4(N) of 64x32 warp tiles.
// NORM: A-load applies relu(a*g_scale[c]+g_shift[c])  (fused BatchNorm+ReLU)
// STATS: epilogue accumulates per-column sum/sumsq into g_bnsum/g_bnsq
// OUTBF16: write packed bf16 to g_hnb instead of fp32 C
constexpr int SM_AH = 0;
constexpr int SM_AL = WHALF;
constexpr int SM_BH = 2 * WHALF;
constexpr int SM_BL = 3 * WHALF;
constexpr int SM_TOT = 4 * WHALF;     // 139264

template<bool RELU, bool NORM, bool STATS, bool OUTBF16>
__global__ void __launch_bounds__(256, 1)
mma_gemm(const float* __restrict__ Aext, int Atag, int wmat,
         const float* __restrict__ bias, int rstag, int Ctag, int ldc)
{
    extern __shared__ __align__(16) char smem[];
    u32 sb = smem_u32(smem);
    int tid = threadIdx.x, wid = tid >> 5, lane = tid & 31;
    int row0 = blockIdx.x * 128;
    int colb = blockIdx.y * 128;
    wmat += blockIdx.y;

    const float* A = Aext ? Aext : bufptr(Atag);
    const float* rowscale = rstag ? bufptr(rstag) : nullptr;
    float* C = bufptr(Ctag);

    // async weight copy (hi+lo, 69632B) into SMEM, overlapped with A convert
    {
        const char* src = g_wb + (size_t)wmat * WMAT_BYTES + tid * 16;
        u32 dst = sb + SM_BH + tid * 16;
#pragma unroll
        for (int i = 0; i < 17; i++)
            cp_async16(dst + i * 4096, src + i * 4096);
    }

    // load A tile (fp32), optional fused norm+relu, split to bf16 hi/lo
    {
        int r = tid >> 1, cb = (tid & 1) * 64;
        bool valid = (row0 + r) < NN;
        const float2* arow = (const float2*)(A + (size_t)(row0 + r) * 128 + cb);
        u32* AH = (u32*)(smem + SM_AH) + (r * WPAD + cb) / 2;
        u32* AL = (u32*)(smem + SM_AL) + (r * WPAD + cb) / 2;
#pragma unroll 8
        for (int i = 0; i < 32; i++) {
            float2 v = valid ? arow[i] : make_float2(0.f, 0.f);
            if (NORM) {
                float2 sc = *(const float2*)&g_scale[cb + 2 * i];
                float2 sh = *(const float2*)&g_shift[cb + 2 * i];
                v.x = fmaxf(v.x * sc.x + sh.x, 0.f);
                v.y = fmaxf(v.y * sc.y + sh.y, 0.f);
            }
            __nv_bfloat16 hx = __float2bfloat16(v.x), hy = __float2bfloat16(v.y);
            __nv_bfloat16 lx = __float2bfloat16(v.x - __bfloat162float(hx));
            __nv_bfloat16 ly = __float2bfloat16(v.y - __bfloat162float(hy));
            AH[i] = (u32)__bfloat16_as_ushort(hx) | ((u32)__bfloat16_as_ushort(hy) << 16);
            AL[i] = (u32)__bfloat16_as_ushort(lx) | ((u32)__bfloat16_as_ushort(ly) << 16);
        }
    }
    cp_async_wait_all();
    __syncthreads();

    int wm = wid >> 2, wn = wid & 3;

    float acc[4][4][4];
#pragma unroll
    for (int i = 0; i < 4; i++)
#pragma unroll
        for (int j = 0; j < 4; j++)
#pragma unroll
            for (int q = 0; q < 4; q++) acc[i][j][q] = 0.f;

    const u32 aoff[3] = { SM_AH, SM_AH, SM_AL };
    const u32 boff[3] = { SM_BH, SM_BL, SM_BH };

#pragma unroll
    for (int p = 0; p < 3; p++) {
        u32 sa0 = sb + aoff[p] + ((wm * 64 + (lane & 15)) * WPAD + (lane >> 4) * 8) * 2;
        u32 sb0 = sb + boff[p] + ((lane & 15) * WPAD + wn * 32) * 2;
#pragma unroll
        for (int k = 0; k < 8; k++) {
            u32 af[4][4];
#pragma unroll
            for (int i = 0; i < 4; i++)
                ldsm_x4(af[i], sa0 + i * 16 * (WPAD * 2) + k * 32);
            u32 bf[4][2];
#pragma unroll
            for (int j = 0; j < 4; j++)
                ldsm_x2t(bf[j], sb0 + k * 16 * (WPAD * 2) + j * 16);
#pragma unroll
            for (int i = 0; i < 4; i++)
#pragma unroll
                for (int j = 0; j < 4; j++)
                    mma16816(acc[i][j], af[i], bf[j]);
        }
    }

    // epilogue
    float csum[8], csq[8];
    if (STATS) {
#pragma unroll
        for (int q = 0; q < 8; q++) { csum[q] = 0.f; csq[q] = 0.f; }
    }
#pragma unroll
    for (int i = 0; i < 4; i++) {
        int ra = row0 + wm * 64 + i * 16 + (lane >> 2);
#pragma unroll
        for (int half = 0; half < 2; half++) {
            int row = ra + half * 8;
            if (row < NN) {
                float rs = rowscale ? rowscale[row] : 1.f;
#pragma unroll
                for (int j = 0; j < 4; j++) {
                    int cc = wn * 32 + j * 8 + (lane & 3) * 2;
                    float b0 = 0.f, b1 = 0.f;
                    if (bias) { b0 = bias[cc]; b1 = bias[cc + 1]; }
                    float v0 = acc[i][j][half * 2 + 0] + rs * b0;
                    float v1 = acc[i][j][half * 2 + 1] + rs * b1;
                    if (RELU) { v0 = fmaxf(v0, 0.f); v1 = fmaxf(v1, 0.f); }
                    if (STATS) {
                        csum[j * 2]     += v0; csq[j * 2]     += v0 * v0;
                        csum[j * 2 + 1] += v1; csq[j * 2 + 1] += v1 * v1;
                    }
                    if (OUTBF16) {
                        g_hnb[(size_t)row * 64 + (cc >> 1)] = pack_bf2(v0, v1);
                    } else {
                        *(float2*)&C[(size_t)row * ldc + colb + cc] = make_float2(v0, v1);
                    }
                }
            }
        }
    }

    if (STATS) {
        float* ssum = (float*)smem;         // SMEM reuse after mma phase
        float* ssq  = ssum + 128;
        __syncthreads();
        if (tid < 128) { ssum[tid] = 0.f; ssq[tid] = 0.f; }
        __syncthreads();
#pragma unroll
        for (int j = 0; j < 4; j++) {
#pragma unroll
            for (int c = 0; c < 2; c++) {
                int col = wn * 32 + j * 8 + (lane & 3) * 2 + c;
                atomicAdd(&ssum[col], csum[j * 2 + c]);
                atomicAdd(&ssq[col],  csq[j * 2 + c]);
            }
        }
        __syncthreads();
        if (tid < 128) {
            atomicAdd(&g_bnsum[tid], ssum[tid]);
            atomicAdd(&g_bnsq[tid],  ssq[tid]);
        }
    }
}

// ---------------- CSR build ----------------
__global__ void zero_deg() {
    int i = blockIdx.x * blockDim.x + threadIdx.x;
    if (i < NN) g_deg[i] = 0;
}
__global__ void hist_kernel(const int* __restrict__ ei) {
    int e = blockIdx.x * blockDim.x + threadIdx.x;
    if (e < NE) atomicAdd(&g_deg[ei[NE + e]], 1);
}
// decoupled 3-phase scan
__global__ void scan_blocks() {          // grid 49 x 1024
    __shared__ int wsum[32];
    int tid = threadIdx.x, lane = tid & 31, w = tid >> 5;
    int i = blockIdx.x * 1024 + tid;
    int v = (i < NN) ? g_deg[i] : 0;
    int x = v;
#pragma unroll
    for (int o = 1; o < 32; o <<= 1) { int t = __shfl_up_sync(~0u, x, o); if (lane >= o) x += t; }
    if (lane == 31) wsum[w] = x;
    __syncthreads();
    if (w == 0) {
        int s = wsum[lane];
#pragma unroll
        for (int o = 1; o < 32; o <<= 1) { int t = __shfl_up_sync(~0u, s, o); if (lane >= o) s += t; }
        wsum[lane] = s;
    }
    __syncthreads();
    int wexcl = (w == 0) ? 0 : wsum[w - 1];
    if (i < NN) g_rowptr[i] = wexcl + x - v;
    if (tid == 1023) g_bsum[blockIdx.x] = wsum[31];
}
__global__ void scan_tops() {            // 1 x 64
    int tid = threadIdx.x;
    __shared__ int sh[64];
    __shared__ int w0tot;
    int v = (tid < 49) ? g_bsum[tid] : 0;
    int lane = tid & 31, w = tid >> 5;
    int x = v;
#pragma unroll
    for (int o = 1; o < 32; o <<= 1) { int t = __shfl_up_sync(~0u, x, o); if (lane >= o) x += t; }
    if (w == 0 && lane == 31) w0tot = x;
    __syncthreads();
    int incl = x + (w == 1 ? w0tot : 0);
    sh[tid] = incl - v;
    __syncthreads();
    if (tid < 49) g_boff[tid] = sh[tid];
}
__global__ void scan_apply() {
    int i = blockIdx.x * blockDim.x + threadIdx.x;
    if (i >= NN) return;
    int rp = g_rowptr[i] + g_boff[i >> 10];
    g_rowptr[i] = rp;
    g_cursor[i] = rp;
    g_degf[i]   = (float)g_deg[i];
    if (i == 0) g_rowptr[NN] = NE;
}
__global__ void scatter_kernel(const int* __restrict__ ei) {
    int e = blockIdx.x * blockDim.x + threadIdx.x;
    if (e >= NE) return;
    int s = ei[e], d = ei[NE + e];
    int p = atomicAdd(&g_cursor[d], 1);
    g_csrc[p] = s;
    g_ceid[p] = e;
}
// Eagg[n,0:32] = sum over in-edges of edge_attr[e,:]; cols 32..127 zeroed (K-pad)
__global__ void eagg_kernel(const float* __restrict__ edge_attr) {
    int w = (blockIdx.x * blockDim.x + threadIdx.x) >> 5;
    if (w >= NN) return;
    int lane = threadIdx.x & 31;
    float acc = 0.f;
    int p0 = g_rowptr[w], p1 = g_rowptr[w + 1];
    for (int p = p0; p < p1; p++) {
        int e = g_ceid[p];
        acc += edge_attr[e * EDIM + lane];
    }
    g_eagg[w * 128 + lane] = acc;
    g_eagg[w * 128 + 32 + lane] = 0.f;
    g_eagg[w * 128 + 64 + lane] = 0.f;
    g_eagg[w * 128 + 96 + lane] = 0.f;
}

// ---------------- GINE aggregation: agg[n] += sum hn_bf16[src] (CSR, atomic-free) ----------------
__global__ void gine_aggregate() {
    int w = (blockIdx.x * blockDim.x + threadIdx.x) >> 5;
    if (w >= NN) return;
    int lane = threadIdx.x & 31;
    float4 acc = *(const float4*)&g_agg[w * HD + lane * 4];
    int p0 = g_rowptr[w], p1 = g_rowptr[w + 1];
    for (int p = p0; p < p1; p++) {
        int s = g_csrc[p];
        u32 a0 = g_hnb[(size_t)s * 64 + lane * 2];
        u32 a1 = g_hnb[(size_t)s * 64 + lane * 2 + 1];
        acc.x += bf_lo(a0); acc.y += bf_hi(a0);
        acc.z += bf_lo(a1); acc.w += bf_hi(a1);
    }
    *(float4*)&g_agg[w * HD + lane * 4] = acc;
}

// ---------------- BatchNorm scalars ----------------
__global__ void bn_zero() {
    int c = threadIdx.x;
    if (c < HD) { g_bnsum[c] = 0.f; g_bnsq[c] = 0.f; }
}
__global__ void bn_final(const float* __restrict__ gamma, const float* __restrict__ beta) {
    int c = threadIdx.x;
    if (c >= HD) return;
    float mu  = g_bnsum[c] / (float)NN;
    float var = g_bnsq[c] / (float)NN - mu * mu;
    float sc  = gamma[c] * rsqrtf(var + EPSF);
    g_scale[c] = sc;
    g_shift[c] = beta[c] - mu * sc;
}

// ---------------- GAT ----------------
__global__ void gat_node1(const float* __restrict__ att_src, const float* __restrict__ att_dst) {
    int n = (blockIdx.x * blockDim.x + threadIdx.x) >> 5;
    if (n >= NN) return;
    int lane = threadIdx.x & 31;
    float s[4], d[4];
#pragma unroll
    for (int h = 0; h < 4; h++) {
        float4 hv = *(const float4*)&g_hfeat[(size_t)n * 512 + h * 128 + lane * 4];
        float4 a1 = *(const float4*)&att_src[h * 128 + lane * 4];
        float4 a2 = *(const float4*)&att_dst[h * 128 + lane * 4];
        float ps = hv.x * a1.x + hv.y * a1.y + hv.z * a1.z + hv.w * a1.w;
        float pd = hv.x * a2.x + hv.y * a2.y + hv.z * a2.z + hv.w * a2.w;
#pragma unroll
        for (int off = 16; off > 0; off >>= 1) {
            ps += __shfl_xor_sync(0xffffffffu, ps, off);
            pd += __shfl_xor_sync(0xffffffffu, pd, off);
        }
        s[h] = ps; d[h] = pd;
    }
    if (lane == 0) {
#pragma unroll
        for (int h = 0; h < 4; h++) {
            g_as[n * 4 + h] = s[h];
            g_ad[n * 4 + h] = d[h];
        }
    }
}
// merged GAT: per-node softmax (max, denom) + weighted accumulation, no atomics
__global__ void gat_node_all(const float* __restrict__ bg) {
    int n = (blockIdx.x * blockDim.x + threadIdx.x) >> 5;
    if (n >= NN) return;
    int lane = threadIdx.x & 31;
    float4 asn = *(const float4*)&g_as[n * 4];
    float4 adn = *(const float4*)&g_ad[n * 4];
    float sl0 = lrelu(asn.x + adn.x), sl1 = lrelu(asn.y + adn.y);
    float sl2 = lrelu(asn.z + adn.z), sl3 = lrelu(asn.w + adn.w);
    int p0 = g_rowptr[n], p1 = g_rowptr[n + 1];

    // pass 1: max (lanes split edges; init with self logit)
    float m0 = sl0, m1 = sl1, m2 = sl2, m3 = sl3;
    for (int p = p0 + lane; p < p1; p += 32) {
        float4 a = *(const float4*)&g_as[g_csrc[p] * 4];
        m0 = fmaxf(m0, lrelu(a.x + adn.x)); m1 = fmaxf(m1, lrelu(a.y + adn.y));
        m2 = fmaxf(m2, lrelu(a.z + adn.z)); m3 = fmaxf(m3, lrelu(a.w + adn.w));
    }
#pragma unroll
    for (int o = 16; o > 0; o >>= 1) {
        m0 = fmaxf(m0, __shfl_xor_sync(~0u, m0, o));
        m1 = fmaxf(m1, __shfl_xor_sync(~0u, m1, o));
        m2 = fmaxf(m2, __shfl_xor_sync(~0u, m2, o));
        m3 = fmaxf(m3, __shfl_xor_sync(~0u, m3, o));
    }
    // pass 2: denom
    float d0 = 0.f, d1 = 0.f, d2 = 0.f, d3 = 0.f;
    for (int p = p0 + lane; p < p1; p += 32) {
        float4 a = *(const float4*)&g_as[g_csrc[p] * 4];
        d0 += __expf(lrelu(a.x + adn.x) - m0); d1 += __expf(lrelu(a.y + adn.y) - m1);
        d2 += __expf(lrelu(a.z + adn.z) - m2); d3 += __expf(lrelu(a.w + adn.w) - m3);
    }
#pragma unroll
    for (int o = 16; o > 0; o >>= 1) {
        d0 += __shfl_xor_sync(~0u, d0, o); d1 += __shfl_xor_sync(~0u, d1, o);
        d2 += __shfl_xor_sync(~0u, d2, o); d3 += __shfl_xor_sync(~0u, d3, o);
    }
    d0 += __expf(sl0 - m0); d1 += __expf(sl1 - m1);
    d2 += __expf(sl2 - m2); d3 += __expf(sl3 - m3);
    float i0 = 1.f / d0, i1 = 1.f / d1, i2 = 1.f / d2, i3 = 1.f / d3;

    // pass 3: weighted accumulation (all lanes per edge, feature-parallel)
    float w0 = __expf(sl0 - m0) * i0, w1 = __expf(sl1 - m1) * i1;
    float w2 = __expf(sl2 - m2) * i2, w3 = __expf(sl3 - m3) * i3;
    size_t base = (size_t)n * 512 + lane * 4;
    float4 h0 = *(const float4*)&g_hfeat[base];
    float4 h1 = *(const float4*)&g_hfeat[base + 128];
    float4 h2 = *(const float4*)&g_hfeat[base + 256];
    float4 h3 = *(const float4*)&g_hfeat[base + 384];
    float4 A0 = { w0 * h0.x, w0 * h0.y, w0 * h0.z, w0 * h0.w };
    float4 A1 = { w1 * h1.x, w1 * h1.y, w1 * h1.z, w1 * h1.w };
    float4 A2 = { w2 * h2.x, w2 * h2.y, w2 * h2.z, w2 * h2.w };
    float4 A3 = { w3 * h3.x, w3 * h3.y, w3 * h3.z, w3 * h3.w };
    for (int p = p0; p < p1; p++) {
        int s = g_csrc[p];
        float4 a = *(const float4*)&g_as[s * 4];
        float e0 = __expf(lrelu(a.x + adn.x) - m0) * i0;
        float e1 = __expf(lrelu(a.y + adn.y) - m1) * i1;
        float e2 = __expf(lrelu(a.z + adn.z) - m2) * i2;
        float e3 = __expf(lrelu(a.w + adn.w) - m3) * i3;
        size_t sbx = (size_t)s * 512 + lane * 4;
        float4 v0 = *(const float4*)&g_hfeat[sbx];
        float4 v1 = *(const float4*)&g_hfeat[sbx + 128];
        float4 v2 = *(const float4*)&g_hfeat[sbx + 256];
        float4 v3 = *(const float4*)&g_hfeat[sbx + 384];
        A0.x += e0 * v0.x; A0.y += e0 * v0.y; A0.z += e0 * v0.z; A0.w += e0 * v0.w;
        A1.x += e1 * v1.x; A1.y += e1 * v1.y; A1.z += e1 * v1.z; A1.w += e1 * v1.w;
        A2.x += e2 * v2.x; A2.y += e2 * v2.y; A2.z += e2 * v2.z; A2.w += e2 * v2.w;
        A3.x += e3 * v3.x; A3.y += e3 * v3.y; A3.z += e3 * v3.z; A3.w += e3 * v3.w;
    }
    float4 bg4 = *(const float4*)&bg[lane * 4];
    float4 o4;
    o4.x = (A0.x + A1.x + A2.x + A3.x) * 0.25f + bg4.x;
    o4.y = (A0.y + A1.y + A2.y + A3.y) * 0.25f + bg4.y;
    o4.z = (A0.z + A1.z + A2.z + A3.z) * 0.25f + bg4.z;
    o4.w = (A0.w + A1.w + A2.w + A3.w) * 0.25f + bg4.w;
    *(float4*)&g_x[(size_t)n * HD + lane * 4] = o4;
}

// ---------------- pooling + fc ----------------
__device__ __forceinline__ int lbound(const int* a, int n, int key) {
    int lo = 0, hi = n;
    while (lo < hi) { int mid = (lo + hi) >> 1; if (a[mid] < key) lo = mid + 1; else hi = mid; }
    return lo;
}
__global__ void pool_kernel(const int* __restrict__ batch) {
    int g = blockIdx.x;
    int c = threadIdx.x;   // 128 threads
    __shared__ int slo, shi;
    if (c == 0) { slo = lbound(batch, NN, g); shi = lbound(batch, NN, g + 1); }
    __syncthreads();
    int lo = slo, hi = shi;
    float a0 = 0.f, a1 = 0.f, a2 = 0.f, a3 = 0.f;
    int n = lo;
    for (; n + 4 <= hi; n += 4) {
        a0 += g_x[(size_t)n * HD + c];
        a1 += g_x[(size_t)(n + 1) * HD + c];
        a2 += g_x[(size_t)(n + 2) * HD + c];
        a3 += g_x[(size_t)(n + 3) * HD + c];
    }
    for (; n < hi; n++) a0 += g_x[(size_t)n * HD + c];
    float s = (a0 + a1) + (a2 + a3);
    g_pool[g * HD + c] = s / fmaxf((float)(hi - lo), 1.f);
}
__global__ void final_kernel(const float* __restrict__ Wfc, const float* __restrict__ bfc,
                             float* __restrict__ out) {
    int idx = blockIdx.x * blockDim.x + threadIdx.x;
    if (idx >= NG * NOUT) return;
    int g = idx / NOUT, o = idx % NOUT;
    float s = bfc[o];
#pragma unroll 8
    for (int k = 0; k < HD; k++) s += g_pool[g * HD + k] * Wfc[k * NOUT + o];
    out[idx] = s;
}

// ---------------- driver (kernel launches only — graph-capture safe) ----------------
extern "C" void kernel_launch(void* const* d_in, const int* in_sizes, int n_in,
                              void* d_out, int out_size) {
    const float* x_in      = (const float*)d_in[0];
    const float* edge_attr = (const float*)d_in[1];
    const int*   ei        = (const int*)d_in[2];
    const int*   batch     = (const int*)d_in[3];
    const float* Wn   = (const float*)d_in[4];
    const float* bn_b = (const float*)d_in[5];
    const float* We   = (const float*)d_in[6];
    const float* be_b = (const float*)d_in[7];
    const float* W1   = (const float*)d_in[8];
    const float* b1   = (const float*)d_in[9];
    const float* W2   = (const float*)d_in[10];
    const float* b2   = (const float*)d_in[11];
    const float* gamma= (const float*)d_in[12];
    const float* beta = (const float*)d_in[13];
    const float* Wg   = (const float*)d_in[14];
    const float* att_src = (const float*)d_in[15];
    const float* att_dst = (const float*)d_in[16];
    const float* bg   = (const float*)d_in[17];
    const float* Wfc  = (const float*)d_in[18];
    const float* bfc  = (const float*)d_in[19];
    float* out = (float*)d_out;

    // opt into >48KB dynamic SMEM for every GEMM instantiation used
    cudaFuncSetAttribute(mma_gemm<false,false,false,true >, cudaFuncAttributeMaxDynamicSharedMemorySize, SM_TOT);
    cudaFuncSetAttribute(mma_gemm<false,true ,false,true >, cudaFuncAttributeMaxDynamicSharedMemorySize, SM_TOT);
    cudaFuncSetAttribute(mma_gemm<false,false,false,false>, cudaFuncAttributeMaxDynamicSharedMemorySize, SM_TOT);
    cudaFuncSetAttribute(mma_gemm<true ,false,false,false>, cudaFuncAttributeMaxDynamicSharedMemorySize, SM_TOT);
    cudaFuncSetAttribute(mma_gemm<false,false,true ,false>, cudaFuncAttributeMaxDynamicSharedMemorySize, SM_TOT);
    cudaFuncSetAttribute(mma_gemm<false,true ,false,false>, cudaFuncAttributeMaxDynamicSharedMemorySize, SM_TOT);

    const int TB = 256;
    const int NODE_BLK = (NN + TB - 1) / TB;
    const int EDGE_BLK = (NE + TB - 1) / TB;
    const int WARP_BLK = (NN * 32 + TB - 1) / TB;
    const dim3 GEMM_G(391, 1);
    const dim3 GEMM_G4(391, 4);

    // ---- graph structure + weight prep (layer-invariant) ----
    zero_deg<<<NODE_BLK, TB>>>();
    hist_kernel<<<EDGE_BLK, TB>>>(ei);
    prep_weights<<<NMAT, 256>>>(Wn, W1, W2, We, Wg);
    scan_blocks<<<49, 1024>>>();
    scan_tops<<<1, 64>>>();
    scan_apply<<<NODE_BLK, TB>>>();
    scatter_kernel<<<EDGE_BLK, TB>>>(ei);
    eagg_kernel<<<WARP_BLK, TB>>>(edge_attr);

    // ---- 10 GINE layers ----
    for (int l = 0; l < NL; l++) {
        // hn = (norm_relu(o) for l>0 else x_in) @ Wn + bn_b  -> bf16 g_hnb
        if (l == 0)
            mma_gemm<false,false,false,true ><<<GEMM_G, 256, SM_TOT>>>(
                x_in, T_NONE, l, bn_b + l * HD, T_NONE, T_HN, HD);
        else
            mma_gemm<false,true ,false,true ><<<GEMM_G, 256, SM_TOT>>>(
                nullptr, T_O, l, bn_b + l * HD, T_NONE, T_HN, HD);
        // agg = Eagg @ We + deg*be_b
        mma_gemm<false,false,false,false><<<GEMM_G, 256, SM_TOT>>>(
            nullptr, T_EA, 30 + l, be_b + l * HD, T_DEGF, T_AGG, HD);
        // agg += sum_{in-edges} hn[src]
        gine_aggregate<<<WARP_BLK, TB>>>();
        // t = relu(agg @ W1 + b1)
        mma_gemm<true ,false,false,false><<<GEMM_G, 256, SM_TOT>>>(
            nullptr, T_AGG, 10 + l, b1 + l * HD, T_NONE, T_T, HD);
        // o = t @ W2 + b2, with fused BN-stats accumulation
        bn_zero<<<1, 128>>>();
        mma_gemm<false,false,true ,false><<<GEMM_G, 256, SM_TOT>>>(
            nullptr, T_T, 20 + l, b2 + l * HD, T_NONE, T_O, HD);
        bn_final<<<1, 128>>>(gamma + l * HD, beta + l * HD);
    }

    // ---- GAT (A-load applies layer-9 norm+relu) ----
    mma_gemm<false,true ,false,false><<<GEMM_G4, 256, SM_TOT>>>(
        nullptr, T_O, 40, nullptr, T_NONE, T_HF, 512);
    gat_node1<<<WARP_BLK, TB>>>(att_src, att_dst);
    gat_node_all<<<WARP_BLK, TB>>>(bg);

    // ---- pool + fc ----
    pool_kernel<<<NG, 128>>>(batch);
    final_kernel<<<(NG * NOUT + TB - 1) / TB, TB>>>(Wfc, bfc, out);
}

// round 7
// speedup vs baseline: 1.3024x; 1.0923x over previous
#include <cuda_runtime.h>
#include <cuda_bf16.h>

// ---------------- problem constants ----------------
constexpr int NN   = 50000;   // nodes
constexpr int NE   = 512000;  // edges
constexpr int HD   = 128;     // hidden
constexpr int EDIM = 32;      // edge dim
constexpr int NL   = 10;      // GINE layers
constexpr int NG   = 64;      // graphs
constexpr int NOUT = 10;
constexpr float EPSF  = 1e-5f;
constexpr float SLOPE = 0.2f;

typedef unsigned long long u64;
typedef unsigned int u32;

// ---------------- generic helpers ----------------
__device__ __forceinline__ float lrelu(float v) { return v < 0.f ? SLOPE * v : v; }
__device__ __forceinline__ u32 smem_u32(const void* p) {
    u32 a; asm("{ .reg .u64 t; cvta.to.shared.u64 t, %1; cvt.u32.u64 %0, t; }" : "=r"(a) : "l"(p));
    return a;
}
__device__ __forceinline__ u32 pack_bf2(float a, float b) {
    return (u32)__bfloat16_as_ushort(__float2bfloat16(a)) |
           ((u32)__bfloat16_as_ushort(__float2bfloat16(b)) << 16);
}
__device__ __forceinline__ float bf_lo(u32 v) {
    return __bfloat162float(__ushort_as_bfloat16((unsigned short)(v & 0xffff)));
}
__device__ __forceinline__ float bf_hi(u32 v) {
    return __bfloat162float(__ushort_as_bfloat16((unsigned short)(v >> 16)));
}

// ---------------- mma.sync helpers (plain sm_100-safe PTX) ----------------
__device__ __forceinline__ void ldsm_x4(u32* r, u32 addr) {
    asm volatile("ldmatrix.sync.aligned.m8n8.x4.shared.b16 {%0,%1,%2,%3}, [%4];"
                 : "=r"(r[0]), "=r"(r[1]), "=r"(r[2]), "=r"(r[3]) : "r"(addr));
}
__device__ __forceinline__ void ldsm_x2t(u32* r, u32 addr) {
    asm volatile("ldmatrix.sync.aligned.m8n8.x2.trans.shared.b16 {%0,%1}, [%2];"
                 : "=r"(r[0]), "=r"(r[1]) : "r"(addr));
}
__device__ __forceinline__ void mma16816(float* c, const u32* a, const u32* b) {
    asm volatile("mma.sync.aligned.m16n8k16.row.col.f32.bf16.bf16.f32 "
                 "{%0,%1,%2,%3}, {%4,%5,%6,%7}, {%8,%9}, {%0,%1,%2,%3};"
                 : "+f"(c[0]), "+f"(c[1]), "+f"(c[2]), "+f"(c[3])
                 : "r"(a[0]), "r"(a[1]), "r"(a[2]), "r"(a[3]), "r"(b[0]), "r"(b[1]));
}
__device__ __forceinline__ void cp_async16(u32 dst, const void* src) {
    asm volatile("cp.async.cg.shared.global [%0], [%1], 16;" :: "r"(dst), "l"(src));
}
__device__ __forceinline__ void cp_async_wait_all() {
    asm volatile("cp.async.commit_group;");
    asm volatile("cp.async.wait_group 0;" ::: "memory");
}

// ---------------- device scratch (no allocs allowed) ----------------
__device__ __align__(16) u32   g_hnb[NN * 64];          // hn in packed bf16x2
__device__ __align__(16) float g_agg[NN * HD];
__device__ __align__(16) float g_agg10[(size_t)NL * NN * HD];  // precomputed edge terms
__device__ __align__(16) float g_t[NN * HD];
__device__ __align__(16) float g_o[NN * HD];
__device__ __align__(16) float g_x[NN * HD];
__device__ __align__(16) float g_hfeat[NN * 4 * HD];    // GAT features [N,4,128]
__device__ __align__(16) float g_eagg[NN * EDIM];
__device__           float g_degf[NN];
__device__           int   g_deg[NN];
__device__           int   g_rowptr[NN + 1];
__device__           int   g_cursor[NN];
__device__           int   g_csrc[NE];
__device__           int   g_ceid[NE];
__device__           int   g_bsum[64];
__device__           int   g_boff[64];
__device__ __align__(16) float g_as[NN * 4];
__device__ __align__(16) float g_ad[NN * 4];
__device__ __align__(16) float g_bnsum[HD];
__device__ __align__(16) float g_bnsq[HD];
__device__ __align__(16) float g_scale[HD];
__device__ __align__(16) float g_shift[HD];
__device__ __align__(16) float g_pool[NG * HD];

// Prepped weights: 44 matrices, each hi (34816B) + lo (34816B), row-major [K][136] bf16.
// m: 0..9 Wn[l], 10..19 W1[l], 20..29 W2[l], 30..39 We[l] (K-padded: rows 0..31 live),
// 40..43 Wg col blocks
constexpr int NMAT = 44;
constexpr int WPAD = 136;
constexpr int WHALF = 128 * WPAD * 2;           // 34816 bytes per half
constexpr int WMAT_BYTES = 2 * WHALF;           // 69632 bytes per matrix
__device__ __align__(16) char g_wb[(size_t)NMAT * WMAT_BYTES];

enum BufTag { T_NONE = 0, T_AGG, T_T, T_O, T_HF };
__device__ __forceinline__ float* bufptr(int t) {
    switch (t) {
        case T_AGG:  return g_agg;
        case T_T:    return g_t;
        case T_O:    return g_o;
        case T_HF:   return g_hfeat;
        default:     return nullptr;
    }
}

// ---------------- weight prep: fp32 [K,N] -> bf16 hi/lo, padded row-major ----------------
__global__ void prep_weights(const float* __restrict__ Wn, const float* __restrict__ W1,
                             const float* __restrict__ W2, const float* __restrict__ We,
                             const float* __restrict__ Wg) {
    int m = blockIdx.x;
    char* dst = g_wb + (size_t)m * WMAT_BYTES;
    for (int idx = threadIdx.x; idx < 16384; idx += blockDim.x) {
        int k = idx >> 7, n = idx & 127;
        float v;
        if (m < 10)       v = Wn[(size_t)m * 16384 + k * 128 + n];
        else if (m < 20)  v = W1[(size_t)(m - 10) * 16384 + k * 128 + n];
        else if (m < 30)  v = W2[(size_t)(m - 20) * 16384 + k * 128 + n];
        else if (m < 40)  v = (k < EDIM) ? We[(size_t)(m - 30) * EDIM * 128 + k * 128 + n] : 0.f;
        else              v = Wg[(size_t)k * 512 + (m - 40) * 128 + n];
        __nv_bfloat16 h = __float2bfloat16(v);
        __nv_bfloat16 l = __float2bfloat16(v - __bfloat162float(h));
        ((__nv_bfloat16*)dst)[k * WPAD + n]           = h;
        ((__nv_bfloat16*)(dst + WHALF))[k * WPAD + n] = l;
    }
}

// ---------------- main tensor-core GEMM (M-tile 64, K=128, occupancy 2) ----------------
// bf16x3 emulation of fp32: AhWh + AhWl + AlWh, fp32 accumulate.
// 256 threads, 64x128 tile/CTA, 8 warps as 2(M)x4(N) of 32x32 warp tiles.
constexpr int AHALF = 64 * WPAD * 2;   // 17408
constexpr int SM_AH = 0;
constexpr int SM_AL = AHALF;           // 17408
constexpr int SM_BH = 2 * AHALF;       // 34816
constexpr int SM_BL = 2 * AHALF + WHALF;
constexpr int SM_TOT = 2 * AHALF + 2 * WHALF;   // 104448 -> 2 CTAs/SM

template<bool RELU, bool NORM, bool STATS, bool OUTBF16>
__global__ void __launch_bounds__(256, 2)
mma_gemm(const float* __restrict__ Aext, int Atag, int wmat,
         const float* __restrict__ bias, int Ctag, int ldc)
{
    extern __shared__ __align__(16) char smem[];
    u32 sb = smem_u32(smem);
    int tid = threadIdx.x, wid = tid >> 5, lane = tid & 31;
    int row0 = blockIdx.x * 64;
    int colb = blockIdx.y * 128;
    wmat += blockIdx.y;

    const float* A = Aext ? Aext : bufptr(Atag);
    float* C = bufptr(Ctag);

    // async weight copy (hi+lo, 69632B) into SMEM, overlapped with A convert
    {
        const char* src = g_wb + (size_t)wmat * WMAT_BYTES + tid * 16;
        u32 dst = sb + SM_BH + tid * 16;
#pragma unroll
        for (int i = 0; i < 17; i++)
            cp_async16(dst + i * 4096, src + i * 4096);
    }

    // load A tile (fp32), optional fused norm+relu, split to bf16 hi/lo
    {
        int r = tid >> 2, cb = (tid & 3) * 32;
        bool valid = (row0 + r) < NN;
        const float2* arow = (const float2*)(A + (size_t)(row0 + r) * 128 + cb);
        u32* AH = (u32*)(smem + SM_AH) + ((r * WPAD + cb) >> 1);
        u32* AL = (u32*)(smem + SM_AL) + ((r * WPAD + cb) >> 1);
#pragma unroll 8
        for (int i = 0; i < 16; i++) {
            float2 v = valid ? arow[i] : make_float2(0.f, 0.f);
            if (NORM) {
                float2 sc = *(const float2*)&g_scale[cb + 2 * i];
                float2 sh = *(const float2*)&g_shift[cb + 2 * i];
                v.x = fmaxf(v.x * sc.x + sh.x, 0.f);
                v.y = fmaxf(v.y * sc.y + sh.y, 0.f);
            }
            __nv_bfloat16 hx = __float2bfloat16(v.x), hy = __float2bfloat16(v.y);
            __nv_bfloat16 lx = __float2bfloat16(v.x - __bfloat162float(hx));
            __nv_bfloat16 ly = __float2bfloat16(v.y - __bfloat162float(hy));
            AH[i] = (u32)__bfloat16_as_ushort(hx) | ((u32)__bfloat16_as_ushort(hy) << 16);
            AL[i] = (u32)__bfloat16_as_ushort(lx) | ((u32)__bfloat16_as_ushort(ly) << 16);
        }
    }
    cp_async_wait_all();
    __syncthreads();

    int wm = wid >> 2, wn = wid & 3;

    float acc[2][4][4];
#pragma unroll
    for (int i = 0; i < 2; i++)
#pragma unroll
        for (int j = 0; j < 4; j++)
#pragma unroll
            for (int q = 0; q < 4; q++) acc[i][j][q] = 0.f;

    const u32 aoff[3] = { SM_AH, SM_AH, SM_AL };
    const u32 boff[3] = { SM_BH, SM_BL, SM_BH };

#pragma unroll
    for (int p = 0; p < 3; p++) {
        u32 sa0 = sb + aoff[p] + ((wm * 32 + (lane & 15)) * WPAD + (lane >> 4) * 8) * 2;
        u32 sb0 = sb + boff[p] + ((lane & 15) * WPAD + wn * 32) * 2;
#pragma unroll
        for (int k = 0; k < 8; k++) {
            u32 af[2][4];
#pragma unroll
            for (int i = 0; i < 2; i++)
                ldsm_x4(af[i], sa0 + i * 16 * (WPAD * 2) + k * 32);
            u32 bf[4][2];
#pragma unroll
            for (int j = 0; j < 4; j++)
                ldsm_x2t(bf[j], sb0 + k * 16 * (WPAD * 2) + j * 16);
#pragma unroll
            for (int i = 0; i < 2; i++)
#pragma unroll
                for (int j = 0; j < 4; j++)
                    mma16816(acc[i][j], af[i], bf[j]);
        }
    }

    // epilogue
    float csum[8], csq[8];
    if (STATS) {
#pragma unroll
        for (int q = 0; q < 8; q++) { csum[q] = 0.f; csq[q] = 0.f; }
    }
#pragma unroll
    for (int i = 0; i < 2; i++) {
        int ra = row0 + wm * 32 + i * 16 + (lane >> 2);
#pragma unroll
        for (int half = 0; half < 2; half++) {
            int row = ra + half * 8;
            if (row < NN) {
#pragma unroll
                for (int j = 0; j < 4; j++) {
                    int cc = wn * 32 + j * 8 + (lane & 3) * 2;
                    float b0 = 0.f, b1 = 0.f;
                    if (bias) { b0 = bias[cc]; b1 = bias[cc + 1]; }
                    float v0 = acc[i][j][half * 2 + 0] + b0;
                    float v1 = acc[i][j][half * 2 + 1] + b1;
                    if (RELU) { v0 = fmaxf(v0, 0.f); v1 = fmaxf(v1, 0.f); }
                    if (STATS) {
                        csum[j * 2]     += v0; csq[j * 2]     += v0 * v0;
                        csum[j * 2 + 1] += v1; csq[j * 2 + 1] += v1 * v1;
                    }
                    if (OUTBF16) {
                        g_hnb[(size_t)row * 64 + (cc >> 1)] = pack_bf2(v0, v1);
                    } else {
                        *(float2*)&C[(size_t)row * ldc + colb + cc] = make_float2(v0, v1);
                    }
                }
            }
        }
    }

    if (STATS) {
        float* ssum = (float*)smem;         // SMEM reuse after mma phase
        float* ssq  = ssum + 128;
        __syncthreads();
        if (tid < 128) { ssum[tid] = 0.f; ssq[tid] = 0.f; }
        __syncthreads();
#pragma unroll
        for (int j = 0; j < 4; j++) {
#pragma unroll
            for (int c = 0; c < 2; c++) {
                int col = wn * 32 + j * 8 + (lane & 3) * 2 + c;
                atomicAdd(&ssum[col], csum[j * 2 + c]);
                atomicAdd(&ssq[col],  csq[j * 2 + c]);
            }
        }
        __syncthreads();
        if (tid < 128) {
            atomicAdd(&g_bnsum[tid], ssum[tid]);
            atomicAdd(&g_bnsq[tid],  ssq[tid]);
        }
    }
}

// ---------------- batched We GEMM: g_agg10[l] = Eagg @ We[l] + deg*be_b[l] ----------------
// K=32 (real), M-tile 128, grid (391, 10). B reuses rows 0..31 of prepped g_wb[30+l].
constexpr int EPAD = 40;                 // A row pad for K=32
constexpr int WE_AH = 0;                 // 128*40*2 = 10240
constexpr int WE_AL = 10240;
constexpr int WE_BH = 20480;             // 32*136*2 = 8704
constexpr int WE_BL = 29184;
constexpr int WE_TOT = 37888;

__global__ void __launch_bounds__(256)
we_gemm(const float* __restrict__ be_b_all)
{
    __shared__ __align__(16) char smem[WE_TOT];
    u32 sb = smem_u32(smem);
    int tid = threadIdx.x, wid = tid >> 5, lane = tid & 31;
    int row0 = blockIdx.x * 128;
    int l = blockIdx.y;

    // B copy: hi/lo rows 0..31 of matrix 30+l (first 8704B of each half)
    {
        const char* mat = g_wb + (size_t)(30 + l) * WMAT_BYTES;
        for (int i = tid; i < 544; i += 256) {
            cp_async16(sb + WE_BH + i * 16, mat + i * 16);
            cp_async16(sb + WE_BL + i * 16, mat + WHALF + i * 16);
        }
    }
    // A: Eagg [128 rows x 32 fp32], split hi/lo, pad rows to 40
    {
        int r = tid >> 1, cb = (tid & 1) * 16;
        bool valid = (row0 + r) < NN;
        const float2* arow = (const float2*)(g_eagg + (size_t)(row0 + r) * 32 + cb);
        u32* AH = (u32*)(smem + WE_AH) + ((r * EPAD + cb) >> 1);
        u32* AL = (u32*)(smem + WE_AL) + ((r * EPAD + cb) >> 1);
#pragma unroll
        for (int i = 0; i < 8; i++) {
            float2 v = valid ? arow[i] : make_float2(0.f, 0.f);
            __nv_bfloat16 hx = __float2bfloat16(v.x), hy = __float2bfloat16(v.y);
            __nv_bfloat16 lx = __float2bfloat16(v.x - __bfloat162float(hx));
            __nv_bfloat16 ly = __float2bfloat16(v.y - __bfloat162float(hy));
            AH[i] = (u32)__bfloat16_as_ushort(hx) | ((u32)__bfloat16_as_ushort(hy) << 16);
            AL[i] = (u32)__bfloat16_as_ushort(lx) | ((u32)__bfloat16_as_ushort(ly) << 16);
        }
    }
    cp_async_wait_all();
    __syncthreads();

    int wm = wid >> 2, wn = wid & 3;    // warp tile 64x32
    float acc[4][4][4];
#pragma unroll
    for (int i = 0; i < 4; i++)
#pragma unroll
        for (int j = 0; j < 4; j++)
#pragma unroll
            for (int q = 0; q < 4; q++) acc[i][j][q] = 0.f;

    const u32 aoff[3] = { WE_AH, WE_AH, WE_AL };
    const u32 boff[3] = { WE_BH, WE_BL, WE_BH };
#pragma unroll
    for (int p = 0; p < 3; p++) {
        u32 sa0 = sb + aoff[p] + ((wm * 64 + (lane & 15)) * EPAD + (lane >> 4) * 8) * 2;
        u32 sb0 = sb + boff[p] + ((lane & 15) * WPAD + wn * 32) * 2;
#pragma unroll
        for (int k = 0; k < 2; k++) {
            u32 af[4][4];
#pragma unroll
            for (int i = 0; i < 4; i++)
                ldsm_x4(af[i], sa0 + i * 16 * (EPAD * 2) + k * 32);
            u32 bf[4][2];
#pragma unroll
            for (int j = 0; j < 4; j++)
                ldsm_x2t(bf[j], sb0 + k * 16 * (WPAD * 2) + j * 16);
#pragma unroll
            for (int i = 0; i < 4; i++)
#pragma unroll
                for (int j = 0; j < 4; j++)
                    mma16816(acc[i][j], af[i], bf[j]);
        }
    }

    float* C = g_agg10 + (size_t)l * NN * HD;
    const float* bias = be_b_all + l * HD;
#pragma unroll
    for (int i = 0; i < 4; i++) {
        int ra = row0 + wm * 64 + i * 16 + (lane >> 2);
#pragma unroll
        for (int half = 0; half < 2; half++) {
            int row = ra + half * 8;
            if (row < NN) {
                float rs = g_degf[row];
#pragma unroll
                for (int j = 0; j < 4; j++) {
                    int cc = wn * 32 + j * 8 + (lane & 3) * 2;
                    float v0 = acc[i][j][half * 2 + 0] + rs * bias[cc];
                    float v1 = acc[i][j][half * 2 + 1] + rs * bias[cc + 1];
                    *(float2*)&C[(size_t)row * HD + cc] = make_float2(v0, v1);
                }
            }
        }
    }
}

// ---------------- CSR build ----------------
__global__ void zero_deg() {
    int i = blockIdx.x * blockDim.x + threadIdx.x;
    if (i < NN) g_deg[i] = 0;
}
__global__ void hist_kernel(const int* __restrict__ ei) {
    int e = blockIdx.x * blockDim.x + threadIdx.x;
    if (e < NE) atomicAdd(&g_deg[ei[NE + e]], 1);
}
__global__ void scan_blocks() {          // grid 49 x 1024
    __shared__ int wsum[32];
    int tid = threadIdx.x, lane = tid & 31, w = tid >> 5;
    int i = blockIdx.x * 1024 + tid;
    int v = (i < NN) ? g_deg[i] : 0;
    int x = v;
#pragma unroll
    for (int o = 1; o < 32; o <<= 1) { int t = __shfl_up_sync(~0u, x, o); if (lane >= o) x += t; }
    if (lane == 31) wsum[w] = x;
    __syncthreads();
    if (w == 0) {
        int s = wsum[lane];
#pragma unroll
        for (int o = 1; o < 32; o <<= 1) { int t = __shfl_up_sync(~0u, s, o); if (lane >= o) s += t; }
        wsum[lane] = s;
    }
    __syncthreads();
    int wexcl = (w == 0) ? 0 : wsum[w - 1];
    if (i < NN) g_rowptr[i] = wexcl + x - v;
    if (tid == 1023) g_bsum[blockIdx.x] = wsum[31];
}
__global__ void scan_tops() {            // 1 x 64
    int tid = threadIdx.x;
    __shared__ int sh[64];
    __shared__ int w0tot;
    int v = (tid < 49) ? g_bsum[tid] : 0;
    int lane = tid & 31, w = tid >> 5;
    int x = v;
#pragma unroll
    for (int o = 1; o < 32; o <<= 1) { int t = __shfl_up_sync(~0u, x, o); if (lane >= o) x += t; }
    if (w == 0 && lane == 31) w0tot = x;
    __syncthreads();
    int incl = x + (w == 1 ? w0tot : 0);
    sh[tid] = incl - v;
    __syncthreads();
    if (tid < 49) g_boff[tid] = sh[tid];
}
__global__ void scan_apply() {
    int i = blockIdx.x * blockDim.x + threadIdx.x;
    if (i >= NN) return;
    int rp = g_rowptr[i] + g_boff[i >> 10];
    g_rowptr[i] = rp;
    g_cursor[i] = rp;
    g_degf[i]   = (float)g_deg[i];
    if (i == 0) g_rowptr[NN] = NE;
}
__global__ void scatter_kernel(const int* __restrict__ ei) {
    int e = blockIdx.x * blockDim.x + threadIdx.x;
    if (e >= NE) return;
    int s = ei[e], d = ei[NE + e];
    int p = atomicAdd(&g_cursor[d], 1);
    g_csrc[p] = s;
    g_ceid[p] = e;
}
__global__ void eagg_kernel(const float* __restrict__ edge_attr) {
    int w = (blockIdx.x * blockDim.x + threadIdx.x) >> 5;
    if (w >= NN) return;
    int lane = threadIdx.x & 31;
    float acc = 0.f;
    int p0 = g_rowptr[w], p1 = g_rowptr[w + 1];
    for (int p = p0; p < p1; p++) {
        int e = g_ceid[p];
        acc += edge_attr[e * EDIM + lane];
    }
    g_eagg[w * EDIM + lane] = acc;
}

// ---------------- GINE aggregation: agg[n] = agg10[l][n] + sum hn_bf16[src] ----------------
__global__ void gine_aggregate(int l) {
    int w = (blockIdx.x * blockDim.x + threadIdx.x) >> 5;
    if (w >= NN) return;
    int lane = threadIdx.x & 31;
    float4 acc = *(const float4*)&g_agg10[(size_t)l * NN * HD + (size_t)w * HD + lane * 4];
    int p0 = g_rowptr[w], p1 = g_rowptr[w + 1];
    for (int p = p0; p < p1; p++) {
        int s = g_csrc[p];
        uint2 a = *(const uint2*)&g_hnb[(size_t)s * 64 + lane * 2];
        acc.x += bf_lo(a.x); acc.y += bf_hi(a.x);
        acc.z += bf_lo(a.y); acc.w += bf_hi(a.y);
    }
    *(float4*)&g_agg[(size_t)w * HD + lane * 4] = acc;
}

// ---------------- BatchNorm scalars (self-resetting) ----------------
__global__ void bn_final(const float* __restrict__ gamma, const float* __restrict__ beta) {
    int c = threadIdx.x;
    if (c >= HD) return;
    float su = g_bnsum[c], sq = g_bnsq[c];
    g_bnsum[c] = 0.f;                 // reset for next layer / next replay
    g_bnsq[c]  = 0.f;
    float mu  = su / (float)NN;
    float var = sq / (float)NN - mu * mu;
    float sc  = gamma[c] * rsqrtf(var + EPSF);
    g_scale[c] = sc;
    g_shift[c] = beta[c] - mu * sc;
}

// ---------------- GAT ----------------
__global__ void gat_node1(const float* __restrict__ att_src, const float* __restrict__ att_dst) {
    int n = (blockIdx.x * blockDim.x + threadIdx.x) >> 5;
    if (n >= NN) return;
    int lane = threadIdx.x & 31;
    float s[4], d[4];
#pragma unroll
    for (int h = 0; h < 4; h++) {
        float4 hv = *(const float4*)&g_hfeat[(size_t)n * 512 + h * 128 + lane * 4];
        float4 a1 = *(const float4*)&att_src[h * 128 + lane * 4];
        float4 a2 = *(const float4*)&att_dst[h * 128 + lane * 4];
        float ps = hv.x * a1.x + hv.y * a1.y + hv.z * a1.z + hv.w * a1.w;
        float pd = hv.x * a2.x + hv.y * a2.y + hv.z * a2.z + hv.w * a2.w;
#pragma unroll
        for (int off = 16; off > 0; off >>= 1) {
            ps += __shfl_xor_sync(0xffffffffu, ps, off);
            pd += __shfl_xor_sync(0xffffffffu, pd, off);
        }
        s[h] = ps; d[h] = pd;
    }
    if (lane == 0) {
#pragma unroll
        for (int h = 0; h < 4; h++) {
            g_as[n * 4 + h] = s[h];
            g_ad[n * 4 + h] = d[h];
        }
    }
}
__global__ void gat_node_all(const float* __restrict__ bg) {
    int n = (blockIdx.x * blockDim.x + threadIdx.x) >> 5;
    if (n >= NN) return;
    int lane = threadIdx.x & 31;
    float4 asn = *(const float4*)&g_as[n * 4];
    float4 adn = *(const float4*)&g_ad[n * 4];
    float sl0 = lrelu(asn.x + adn.x), sl1 = lrelu(asn.y + adn.y);
    float sl2 = lrelu(asn.z + adn.z), sl3 = lrelu(asn.w + adn.w);
    int p0 = g_rowptr[n], p1 = g_rowptr[n + 1];

    float m0 = sl0, m1 = sl1, m2 = sl2, m3 = sl3;
    for (int p = p0 + lane; p < p1; p += 32) {
        float4 a = *(const float4*)&g_as[g_csrc[p] * 4];
        m0 = fmaxf(m0, lrelu(a.x + adn.x)); m1 = fmaxf(m1, lrelu(a.y + adn.y));
        m2 = fmaxf(m2, lrelu(a.z + adn.z)); m3 = fmaxf(m3, lrelu(a.w + adn.w));
    }
#pragma unroll
    for (int o = 16; o > 0; o >>= 1) {
        m0 = fmaxf(m0, __shfl_xor_sync(~0u, m0, o));
        m1 = fmaxf(m1, __shfl_xor_sync(~0u, m1, o));
        m2 = fmaxf(m2, __shfl_xor_sync(~0u, m2, o));
        m3 = fmaxf(m3, __shfl_xor_sync(~0u, m3, o));
    }
    float d0 = 0.f, d1 = 0.f, d2 = 0.f, d3 = 0.f;
    for (int p = p0 + lane; p < p1; p += 32) {
        float4 a = *(const float4*)&g_as[g_csrc[p] * 4];
        d0 += __expf(lrelu(a.x + adn.x) - m0); d1 += __expf(lrelu(a.y + adn.y) - m1);
        d2 += __expf(lrelu(a.z + adn.z) - m2); d3 += __expf(lrelu(a.w + adn.w) - m3);
    }
#pragma unroll
    for (int o = 16; o > 0; o >>= 1) {
        d0 += __shfl_xor_sync(~0u, d0, o); d1 += __shfl_xor_sync(~0u, d1, o);
        d2 += __shfl_xor_sync(~0u, d2, o); d3 += __shfl_xor_sync(~0u, d3, o);
    }
    d0 += __expf(sl0 - m0); d1 += __expf(sl1 - m1);
    d2 += __expf(sl2 - m2); d3 += __expf(sl3 - m3);
    float i0 = 1.f / d0, i1 = 1.f / d1, i2 = 1.f / d2, i3 = 1.f / d3;

    float w0 = __expf(sl0 - m0) * i0, w1 = __expf(sl1 - m1) * i1;
    float w2 = __expf(sl2 - m2) * i2, w3 = __expf(sl3 - m3) * i3;
    size_t base = (size_t)n * 512 + lane * 4;
    float4 h0 = *(const float4*)&g_hfeat[base];
    float4 h1 = *(const float4*)&g_hfeat[base + 128];
    float4 h2 = *(const float4*)&g_hfeat[base + 256];
    float4 h3 = *(const float4*)&g_hfeat[base + 384];
    float4 A0 = { w0 * h0.x, w0 * h0.y, w0 * h0.z, w0 * h0.w };
    float4 A1 = { w1 * h1.x, w1 * h1.y, w1 * h1.z, w1 * h1.w };
    float4 A2 = { w2 * h2.x, w2 * h2.y, w2 * h2.z, w2 * h2.w };
    float4 A3 = { w3 * h3.x, w3 * h3.y, w3 * h3.z, w3 * h3.w };
    for (int p = p0; p < p1; p++) {
        int s = g_csrc[p];
        float4 a = *(const float4*)&g_as[s * 4];
        float e0 = __expf(lrelu(a.x + adn.x) - m0) * i0;
        float e1 = __expf(lrelu(a.y + adn.y) - m1) * i1;
        float e2 = __expf(lrelu(a.z + adn.z) - m2) * i2;
        float e3 = __expf(lrelu(a.w + adn.w) - m3) * i3;
        size_t sbx = (size_t)s * 512 + lane * 4;
        float4 v0 = *(const float4*)&g_hfeat[sbx];
        float4 v1 = *(const float4*)&g_hfeat[sbx + 128];
        float4 v2 = *(const float4*)&g_hfeat[sbx + 256];
        float4 v3 = *(const float4*)&g_hfeat[sbx + 384];
        A0.x += e0 * v0.x; A0.y += e0 * v0.y; A0.z += e0 * v0.z; A0.w += e0 * v0.w;
        A1.x += e1 * v1.x; A1.y += e1 * v1.y; A1.z += e1 * v1.z; A1.w += e1 * v1.w;
        A2.x += e2 * v2.x; A2.y += e2 * v2.y; A2.z += e2 * v2.z; A2.w += e2 * v2.w;
        A3.x += e3 * v3.x; A3.y += e3 * v3.y; A3.z += e3 * v3.z; A3.w += e3 * v3.w;
    }
    float4 bg4 = *(const float4*)&bg[lane * 4];
    float4 o4;
    o4.x = (A0.x + A1.x + A2.x + A3.x) * 0.25f + bg4.x;
    o4.y = (A0.y + A1.y + A2.y + A3.y) * 0.25f + bg4.y;
    o4.z = (A0.z + A1.z + A2.z + A3.z) * 0.25f + bg4.z;
    o4.w = (A0.w + A1.w + A2.w + A3.w) * 0.25f + bg4.w;
    *(float4*)&g_x[(size_t)n * HD + lane * 4] = o4;
}

// ---------------- pooling + fc ----------------
__device__ __forceinline__ int lbound(const int* a, int n, int key) {
    int lo = 0, hi = n;
    while (lo < hi) { int mid = (lo + hi) >> 1; if (a[mid] < key) lo = mid + 1; else hi = mid; }
    return lo;
}
__global__ void pool_kernel(const int* __restrict__ batch) {
    int g = blockIdx.x;
    int c = threadIdx.x;
    __shared__ int slo, shi;
    if (c == 0) { slo = lbound(batch, NN, g); shi = lbound(batch, NN, g + 1); }
    __syncthreads();
    int lo = slo, hi = shi;
    float a0 = 0.f, a1 = 0.f, a2 = 0.f, a3 = 0.f;
    int n = lo;
    for (; n + 4 <= hi; n += 4) {
        a0 += g_x[(size_t)n * HD + c];
        a1 += g_x[(size_t)(n + 1) * HD + c];
        a2 += g_x[(size_t)(n + 2) * HD + c];
        a3 += g_x[(size_t)(n + 3) * HD + c];
    }
    for (; n < hi; n++) a0 += g_x[(size_t)n * HD + c];
    float s = (a0 + a1) + (a2 + a3);
    g_pool[g * HD + c] = s / fmaxf((float)(hi - lo), 1.f);
}
__global__ void final_kernel(const float* __restrict__ Wfc, const float* __restrict__ bfc,
                             float* __restrict__ out) {
    int idx = blockIdx.x * blockDim.x + threadIdx.x;
    if (idx >= NG * NOUT) return;
    int g = idx / NOUT, o = idx % NOUT;
    float s = bfc[o];
#pragma unroll 8
    for (int k = 0; k < HD; k++) s += g_pool[g * HD + k] * Wfc[k * NOUT + o];
    out[idx] = s;
}

// ---------------- driver (kernel launches only — graph-capture safe) ----------------
extern "C" void kernel_launch(void* const* d_in, const int* in_sizes, int n_in,
                              void* d_out, int out_size) {
    const float* x_in      = (const float*)d_in[0];
    const float* edge_attr = (const float*)d_in[1];
    const int*   ei        = (const int*)d_in[2];
    const int*   batch     = (const int*)d_in[3];
    const float* Wn   = (const float*)d_in[4];
    const float* bn_b = (const float*)d_in[5];
    const float* We   = (const float*)d_in[6];
    const float* be_b = (const float*)d_in[7];
    const float* W1   = (const float*)d_in[8];
    const float* b1   = (const float*)d_in[9];
    const float* W2   = (const float*)d_in[10];
    const float* b2   = (const float*)d_in[11];
    const float* gamma= (const float*)d_in[12];
    const float* beta = (const float*)d_in[13];
    const float* Wg   = (const float*)d_in[14];
    const float* att_src = (const float*)d_in[15];
    const float* att_dst = (const float*)d_in[16];
    const float* bg   = (const float*)d_in[17];
    const float* Wfc  = (const float*)d_in[18];
    const float* bfc  = (const float*)d_in[19];
    float* out = (float*)d_out;

    cudaFuncSetAttribute(mma_gemm<false,false,false,true >, cudaFuncAttributeMaxDynamicSharedMemorySize, SM_TOT);
    cudaFuncSetAttribute(mma_gemm<false,true ,false,true >, cudaFuncAttributeMaxDynamicSharedMemorySize, SM_TOT);
    cudaFuncSetAttribute(mma_gemm<true ,false,false,false>, cudaFuncAttributeMaxDynamicSharedMemorySize, SM_TOT);
    cudaFuncSetAttribute(mma_gemm<false,false,true ,false>, cudaFuncAttributeMaxDynamicSharedMemorySize, SM_TOT);
    cudaFuncSetAttribute(mma_gemm<false,true ,false,false>, cudaFuncAttributeMaxDynamicSharedMemorySize, SM_TOT);

    const int TB = 256;
    const int NODE_BLK = (NN + TB - 1) / TB;
    const int EDGE_BLK = (NE + TB - 1) / TB;
    const int WARP_BLK = (NN * 32 + TB - 1) / TB;
    const dim3 GEMM_G(782, 1);
    const dim3 GEMM_G4(782, 4);

    // prologue — ordered so launch index 3 is a representative GEMM (ncu samples it)
    prep_weights<<<NMAT, 256>>>(Wn, W1, W2, We, Wg);                 // 0
    zero_deg<<<NODE_BLK, TB>>>();                                    // 1
    hist_kernel<<<EDGE_BLK, TB>>>(ei);                               // 2
    mma_gemm<false,false,false,true ><<<GEMM_G, 256, SM_TOT>>>(      // 3  (profiled)
        x_in, T_NONE, 0, bn_b, T_NONE, HD);                          //    layer-0 hn
    scan_blocks<<<49, 1024>>>();                                     // 4
    scan_tops<<<1, 64>>>();                                          // 5
    scan_apply<<<NODE_BLK, TB>>>();                                  // 6
    scatter_kernel<<<EDGE_BLK, TB>>>(ei);                            // 7
    eagg_kernel<<<WARP_BLK, TB>>>(edge_attr);                        // 8
    we_gemm<<<dim3(391, 10), 256>>>(be_b);                           // 9  all 10 edge terms

    // ---- 10 GINE layers ----
    for (int l = 0; l < NL; l++) {
        if (l > 0)   // hn = norm_relu(o) @ Wn + bn_b  -> bf16 g_hnb
            mma_gemm<false,true ,false,true ><<<GEMM_G, 256, SM_TOT>>>(
                nullptr, T_O, l, bn_b + l * HD, T_NONE, HD);
        gine_aggregate<<<WARP_BLK, TB>>>(l);
        mma_gemm<true ,false,false,false><<<GEMM_G, 256, SM_TOT>>>(
            nullptr, T_AGG, 10 + l, b1 + l * HD, T_T, HD);
        mma_gemm<false,false,true ,false><<<GEMM_G, 256, SM_TOT>>>(
            nullptr, T_T, 20 + l, b2 + l * HD, T_O, HD);
        bn_final<<<1, 128>>>(gamma + l * HD, beta + l * HD);
    }

    // ---- GAT (A-load applies layer-9 norm+relu) ----
    mma_gemm<false,true ,false,false><<<GEMM_G4, 256, SM_TOT>>>(
        nullptr, T_O, 40, nullptr, T_HF, 512);
    gat_node1<<<WARP_BLK, TB>>>(att_src, att_dst);
    gat_node_all<<<WARP_BLK, TB>>>(bg);

    // ---- pool + fc ----
    pool_kernel<<<NG, 128>>>(batch);
    final_kernel<<<(NG * NOUT + TB - 1) / TB, TB>>>(Wfc, bfc, out);
}

// round 8
// speedup vs baseline: 1.3592x; 1.0437x over previous
#include <cuda_runtime.h>
#include <cuda_bf16.h>

// ---------------- problem constants ----------------
constexpr int NN   = 50000;   // nodes
constexpr int NE   = 512000;  // edges
constexpr int HD   = 128;     // hidden
constexpr int EDIM = 32;      // edge dim
constexpr int NL   = 10;      // GINE layers
constexpr int NG   = 64;      // graphs
constexpr int NOUT = 10;
constexpr float EPSF  = 1e-5f;
constexpr float SLOPE = 0.2f;

typedef unsigned long long u64;
typedef unsigned int u32;

// ---------------- generic helpers ----------------
__device__ __forceinline__ float lrelu(float v) { return v < 0.f ? SLOPE * v : v; }
__device__ __forceinline__ u32 smem_u32(const void* p) {
    u32 a; asm("{ .reg .u64 t; cvta.to.shared.u64 t, %1; cvt.u32.u64 %0, t; }" : "=r"(a) : "l"(p));
    return a;
}
__device__ __forceinline__ u32 pack_bf2(float a, float b) {
    return (u32)__bfloat16_as_ushort(__float2bfloat16(a)) |
           ((u32)__bfloat16_as_ushort(__float2bfloat16(b)) << 16);
}
__device__ __forceinline__ float bf_lo(u32 v) {
    return __bfloat162float(__ushort_as_bfloat16((unsigned short)(v & 0xffff)));
}
__device__ __forceinline__ float bf_hi(u32 v) {
    return __bfloat162float(__ushort_as_bfloat16((unsigned short)(v >> 16)));
}

// ---------------- mma.sync helpers (plain sm_100-safe PTX) ----------------
__device__ __forceinline__ void ldsm_x4(u32* r, u32 addr) {
    asm volatile("ldmatrix.sync.aligned.m8n8.x4.shared.b16 {%0,%1,%2,%3}, [%4];"
                 : "=r"(r[0]), "=r"(r[1]), "=r"(r[2]), "=r"(r[3]) : "r"(addr));
}
__device__ __forceinline__ void ldsm_x2t(u32* r, u32 addr) {
    asm volatile("ldmatrix.sync.aligned.m8n8.x2.trans.shared.b16 {%0,%1}, [%2];"
                 : "=r"(r[0]), "=r"(r[1]) : "r"(addr));
}
__device__ __forceinline__ void mma16816(float* c, const u32* a, const u32* b) {
    asm volatile("mma.sync.aligned.m16n8k16.row.col.f32.bf16.bf16.f32 "
                 "{%0,%1,%2,%3}, {%4,%5,%6,%7}, {%8,%9}, {%0,%1,%2,%3};"
                 : "+f"(c[0]), "+f"(c[1]), "+f"(c[2]), "+f"(c[3])
                 : "r"(a[0]), "r"(a[1]), "r"(a[2]), "r"(a[3]), "r"(b[0]), "r"(b[1]));
}
__device__ __forceinline__ void cp_async16(u32 dst, const void* src) {
    asm volatile("cp.async.cg.shared.global [%0], [%1], 16;" :: "r"(dst), "l"(src));
}
__device__ __forceinline__ void cp_async_wait_all() {
    asm volatile("cp.async.commit_group;");
    asm volatile("cp.async.wait_group 0;" ::: "memory");
}

// ---------------- device scratch (no allocs allowed) ----------------
__device__ __align__(16) u32   g_hnb[NN * 64];          // hn in packed bf16x2
__device__ __align__(16) u32   g_hfb[NN * 256];         // GAT features bf16x2 [N,4,128]
__device__ __align__(16) float g_agg[NN * HD];
__device__ __align__(16) float g_agg10[(size_t)NL * NN * HD];  // precomputed edge terms
__device__ __align__(16) float g_t[NN * HD];
__device__ __align__(16) float g_o[NN * HD];
__device__ __align__(16) float g_x[NN * HD];
__device__ __align__(16) float g_eagg[NN * EDIM];
__device__           float g_degf[NN];
__device__           int   g_deg[NN];
__device__           int   g_rowptr[NN + 1];
__device__           int   g_cursor[NN];
__device__           int   g_csrc[NE];
__device__           int   g_ceid[NE];
__device__           int   g_bsum[64];
__device__           int   g_boff[64];
__device__ __align__(16) float g_as[NN * 4];
__device__ __align__(16) float g_ad[NN * 4];
__device__ __align__(16) float g_bnsum[HD];
__device__ __align__(16) float g_bnsq[HD];
__device__ __align__(16) float g_scale[HD];
__device__ __align__(16) float g_shift[HD];
__device__ __align__(16) float g_pool[NG * HD];

// Prepped weights: 44 matrices, each hi (34816B) + lo (34816B), row-major [K][136] bf16.
constexpr int NMAT = 44;
constexpr int WPAD = 136;
constexpr int WHALF = 128 * WPAD * 2;           // 34816 bytes per half
constexpr int WMAT_BYTES = 2 * WHALF;
__device__ __align__(16) char g_wb[(size_t)NMAT * WMAT_BYTES];

enum BufTag { T_NONE = 0, T_AGG, T_T, T_O, T_HNB, T_HFB };
__device__ __forceinline__ float* bufptr(int t) {
    switch (t) {
        case T_AGG:  return g_agg;
        case T_T:    return g_t;
        case T_O:    return g_o;
        default:     return nullptr;
    }
}

// ---------------- weight prep ----------------
__global__ void prep_weights(const float* __restrict__ Wn, const float* __restrict__ W1,
                             const float* __restrict__ W2, const float* __restrict__ We,
                             const float* __restrict__ Wg) {
    int m = blockIdx.x;
    char* dst = g_wb + (size_t)m * WMAT_BYTES;
    for (int idx = threadIdx.x; idx < 16384; idx += blockDim.x) {
        int k = idx >> 7, n = idx & 127;
        float v;
        if (m < 10)       v = Wn[(size_t)m * 16384 + k * 128 + n];
        else if (m < 20)  v = W1[(size_t)(m - 10) * 16384 + k * 128 + n];
        else if (m < 30)  v = W2[(size_t)(m - 20) * 16384 + k * 128 + n];
        else if (m < 40)  v = (k < EDIM) ? We[(size_t)(m - 30) * EDIM * 128 + k * 128 + n] : 0.f;
        else              v = Wg[(size_t)k * 512 + (m - 40) * 128 + n];
        __nv_bfloat16 h = __float2bfloat16(v);
        __nv_bfloat16 l = __float2bfloat16(v - __bfloat162float(h));
        ((__nv_bfloat16*)dst)[k * WPAD + n]           = h;
        ((__nv_bfloat16*)(dst + WHALF))[k * WPAD + n] = l;
    }
}

// ---------------- main tensor-core GEMM (M64xN128, K=128, occupancy 3) ----------------
// bf16x3 fp32 emulation with SINGLE B buffer: pass order AhWh, AlWh (Bh), reload, AhWl (Bl).
constexpr int AHALF = 64 * WPAD * 2;   // 17408
constexpr int SM_AH = 0;
constexpr int SM_AL = AHALF;
constexpr int SM_B  = 2 * AHALF;       // 34816
constexpr int SM_TOT = 2 * AHALF + WHALF;   // 69632 -> 3 CTAs/SM

template<bool RELU, bool NORM, bool STATS, bool OUTBF16>
__global__ void __launch_bounds__(256, 3)
mma_gemm(const float* __restrict__ Aext, int Atag, int wmat,
         const float* __restrict__ bias, int Ctag, int ldc)
{
    extern __shared__ __align__(16) char smem[];
    u32 sb = smem_u32(smem);
    int tid = threadIdx.x, wid = tid >> 5, lane = tid & 31;
    int row0 = blockIdx.x * 64;
    int colb = blockIdx.y * 128;
    wmat += blockIdx.y;

    const float* A = Aext ? Aext : bufptr(Atag);
    float* C = bufptr(Ctag);
    const char* wsrc = g_wb + (size_t)wmat * WMAT_BYTES;

    // async copy B-hi (34816B) into the single B buffer
    for (int i = tid; i < 2176; i += 256)
        cp_async16(sb + SM_B + i * 16, wsrc + i * 16);

    // load A tile (fp32), optional fused norm+relu, split to bf16 hi/lo
    {
        int r = tid >> 2, cb = (tid & 3) * 32;
        bool valid = (row0 + r) < NN;
        const float2* arow = (const float2*)(A + (size_t)(row0 + r) * 128 + cb);
        u32* AH = (u32*)(smem + SM_AH) + ((r * WPAD + cb) >> 1);
        u32* AL = (u32*)(smem + SM_AL) + ((r * WPAD + cb) >> 1);
#pragma unroll 8
        for (int i = 0; i < 16; i++) {
            float2 v = valid ? arow[i] : make_float2(0.f, 0.f);
            if (NORM) {
                float2 sc = *(const float2*)&g_scale[cb + 2 * i];
                float2 sh = *(const float2*)&g_shift[cb + 2 * i];
                v.x = fmaxf(v.x * sc.x + sh.x, 0.f);
                v.y = fmaxf(v.y * sc.y + sh.y, 0.f);
            }
            __nv_bfloat16 hx = __float2bfloat16(v.x), hy = __float2bfloat16(v.y);
            __nv_bfloat16 lx = __float2bfloat16(v.x - __bfloat162float(hx));
            __nv_bfloat16 ly = __float2bfloat16(v.y - __bfloat162float(hy));
            AH[i] = (u32)__bfloat16_as_ushort(hx) | ((u32)__bfloat16_as_ushort(hy) << 16);
            AL[i] = (u32)__bfloat16_as_ushort(lx) | ((u32)__bfloat16_as_ushort(ly) << 16);
        }
    }
    cp_async_wait_all();
    __syncthreads();

    int wm = wid >> 2, wn = wid & 3;

    float acc[2][4][4];
#pragma unroll
    for (int i = 0; i < 2; i++)
#pragma unroll
        for (int j = 0; j < 4; j++)
#pragma unroll
            for (int q = 0; q < 4; q++) acc[i][j][q] = 0.f;

    auto run_pass = [&](u32 a_base) {
        u32 sa0 = sb + a_base + ((wm * 32 + (lane & 15)) * WPAD + (lane >> 4) * 8) * 2;
        u32 sb0 = sb + SM_B + ((lane & 15) * WPAD + wn * 32) * 2;
#pragma unroll
        for (int k = 0; k < 8; k++) {
            u32 af[2][4];
#pragma unroll
            for (int i = 0; i < 2; i++)
                ldsm_x4(af[i], sa0 + i * 16 * (WPAD * 2) + k * 32);
            u32 bf[4][2];
#pragma unroll
            for (int j = 0; j < 4; j++)
                ldsm_x2t(bf[j], sb0 + k * 16 * (WPAD * 2) + j * 16);
#pragma unroll
            for (int i = 0; i < 2; i++)
#pragma unroll
                for (int j = 0; j < 4; j++)
                    mma16816(acc[i][j], af[i], bf[j]);
        }
    };

    run_pass(SM_AH);       // Ah * Wh
    run_pass(SM_AL);       // Al * Wh
    __syncthreads();       // all warps done with B-hi
    for (int i = tid; i < 2176; i += 256)                // reload: B-lo
        cp_async16(sb + SM_B + i * 16, wsrc + WHALF + i * 16);
    cp_async_wait_all();
    __syncthreads();
    run_pass(SM_AH);       // Ah * Wl

    // epilogue
    float csum[8], csq[8];
    if (STATS) {
#pragma unroll
        for (int q = 0; q < 8; q++) { csum[q] = 0.f; csq[q] = 0.f; }
    }
#pragma unroll
    for (int i = 0; i < 2; i++) {
        int ra = row0 + wm * 32 + i * 16 + (lane >> 2);
#pragma unroll
        for (int half = 0; half < 2; half++) {
            int row = ra + half * 8;
            if (row < NN) {
#pragma unroll
                for (int j = 0; j < 4; j++) {
                    int cc = wn * 32 + j * 8 + (lane & 3) * 2;
                    float b0 = 0.f, b1 = 0.f;
                    if (bias) { b0 = bias[cc]; b1 = bias[cc + 1]; }
                    float v0 = acc[i][j][half * 2 + 0] + b0;
                    float v1 = acc[i][j][half * 2 + 1] + b1;
                    if (RELU) { v0 = fmaxf(v0, 0.f); v1 = fmaxf(v1, 0.f); }
                    if (STATS) {
                        csum[j * 2]     += v0; csq[j * 2]     += v0 * v0;
                        csum[j * 2 + 1] += v1; csq[j * 2 + 1] += v1 * v1;
                    }
                    if (OUTBF16) {
                        u32* U = (Ctag == T_HFB) ? g_hfb : g_hnb;
                        U[(size_t)row * (ldc >> 1) + ((colb + cc) >> 1)] = pack_bf2(v0, v1);
                    } else {
                        *(float2*)&C[(size_t)row * ldc + colb + cc] = make_float2(v0, v1);
                    }
                }
            }
        }
    }

    if (STATS) {
        float* ssum = (float*)smem;
        float* ssq  = ssum + 128;
        __syncthreads();
        if (tid < 128) { ssum[tid] = 0.f; ssq[tid] = 0.f; }
        __syncthreads();
#pragma unroll
        for (int j = 0; j < 4; j++) {
#pragma unroll
            for (int c = 0; c < 2; c++) {
                int col = wn * 32 + j * 8 + (lane & 3) * 2 + c;
                atomicAdd(&ssum[col], csum[j * 2 + c]);
                atomicAdd(&ssq[col],  csq[j * 2 + c]);
            }
        }
        __syncthreads();
        if (tid < 128) {
            atomicAdd(&g_bnsum[tid], ssum[tid]);
            atomicAdd(&g_bnsq[tid],  ssq[tid]);
        }
    }
}

// ---------------- batched We GEMM: g_agg10[l] = Eagg @ We[l] + deg*be_b[l] ----------------
constexpr int EPAD = 40;
constexpr int WE_AH = 0;
constexpr int WE_AL = 10240;
constexpr int WE_BH = 20480;
constexpr int WE_BL = 29184;
constexpr int WE_TOT = 37888;

__global__ void __launch_bounds__(256)
we_gemm(const float* __restrict__ be_b_all)
{
    __shared__ __align__(16) char smem[WE_TOT];
    u32 sb = smem_u32(smem);
    int tid = threadIdx.x, wid = tid >> 5, lane = tid & 31;
    int row0 = blockIdx.x * 128;
    int l = blockIdx.y;

    {
        const char* mat = g_wb + (size_t)(30 + l) * WMAT_BYTES;
        for (int i = tid; i < 544; i += 256) {
            cp_async16(sb + WE_BH + i * 16, mat + i * 16);
            cp_async16(sb + WE_BL + i * 16, mat + WHALF + i * 16);
        }
    }
    {
        int r = tid >> 1, cb = (tid & 1) * 16;
        bool valid = (row0 + r) < NN;
        const float2* arow = (const float2*)(g_eagg + (size_t)(row0 + r) * 32 + cb);
        u32* AH = (u32*)(smem + WE_AH) + ((r * EPAD + cb) >> 1);
        u32* AL = (u32*)(smem + WE_AL) + ((r * EPAD + cb) >> 1);
#pragma unroll
        for (int i = 0; i < 8; i++) {
            float2 v = valid ? arow[i] : make_float2(0.f, 0.f);
            __nv_bfloat16 hx = __float2bfloat16(v.x), hy = __float2bfloat16(v.y);
            __nv_bfloat16 lx = __float2bfloat16(v.x - __bfloat162float(hx));
            __nv_bfloat16 ly = __float2bfloat16(v.y - __bfloat162float(hy));
            AH[i] = (u32)__bfloat16_as_ushort(hx) | ((u32)__bfloat16_as_ushort(hy) << 16);
            AL[i] = (u32)__bfloat16_as_ushort(lx) | ((u32)__bfloat16_as_ushort(ly) << 16);
        }
    }
    cp_async_wait_all();
    __syncthreads();

    int wm = wid >> 2, wn = wid & 3;
    float acc[4][4][4];
#pragma unroll
    for (int i = 0; i < 4; i++)
#pragma unroll
        for (int j = 0; j < 4; j++)
#pragma unroll
            for (int q = 0; q < 4; q++) acc[i][j][q] = 0.f;

    const u32 aoff[3] = { WE_AH, WE_AH, WE_AL };
    const u32 boff[3] = { WE_BH, WE_BL, WE_BH };
#pragma unroll
    for (int p = 0; p < 3; p++) {
        u32 sa0 = sb + aoff[p] + ((wm * 64 + (lane & 15)) * EPAD + (lane >> 4) * 8) * 2;
        u32 sb0 = sb + boff[p] + ((lane & 15) * WPAD + wn * 32) * 2;
#pragma unroll
        for (int k = 0; k < 2; k++) {
            u32 af[4][4];
#pragma unroll
            for (int i = 0; i < 4; i++)
                ldsm_x4(af[i], sa0 + i * 16 * (EPAD * 2) + k * 32);
            u32 bf[4][2];
#pragma unroll
            for (int j = 0; j < 4; j++)
                ldsm_x2t(bf[j], sb0 + k * 16 * (WPAD * 2) + j * 16);
#pragma unroll
            for (int i = 0; i < 4; i++)
#pragma unroll
                for (int j = 0; j < 4; j++)
                    mma16816(acc[i][j], af[i], bf[j]);
        }
    }

    float* C = g_agg10 + (size_t)l * NN * HD;
    const float* bias = be_b_all + l * HD;
#pragma unroll
    for (int i = 0; i < 4; i++) {
        int ra = row0 + wm * 64 + i * 16 + (lane >> 2);
#pragma unroll
        for (int half = 0; half < 2; half++) {
            int row = ra + half * 8;
            if (row < NN) {
                float rs = g_degf[row];
#pragma unroll
                for (int j = 0; j < 4; j++) {
                    int cc = wn * 32 + j * 8 + (lane & 3) * 2;
                    float v0 = acc[i][j][half * 2 + 0] + rs * bias[cc];
                    float v1 = acc[i][j][half * 2 + 1] + rs * bias[cc + 1];
                    *(float2*)&C[(size_t)row * HD + cc] = make_float2(v0, v1);
                }
            }
        }
    }
}

// ---------------- CSR build ----------------
__global__ void zero_deg() {
    int i = blockIdx.x * blockDim.x + threadIdx.x;
    if (i < NN) g_deg[i] = 0;
}
__global__ void hist_kernel(const int* __restrict__ ei) {
    int e = blockIdx.x * blockDim.x + threadIdx.x;
    if (e < NE) atomicAdd(&g_deg[ei[NE + e]], 1);
}
__global__ void scan_blocks() {
    __shared__ int wsum[32];
    int tid = threadIdx.x, lane = tid & 31, w = tid >> 5;
    int i = blockIdx.x * 1024 + tid;
    int v = (i < NN) ? g_deg[i] : 0;
    int x = v;
#pragma unroll
    for (int o = 1; o < 32; o <<= 1) { int t = __shfl_up_sync(~0u, x, o); if (lane >= o) x += t; }
    if (lane == 31) wsum[w] = x;
    __syncthreads();
    if (w == 0) {
        int s = wsum[lane];
#pragma unroll
        for (int o = 1; o < 32; o <<= 1) { int t = __shfl_up_sync(~0u, s, o); if (lane >= o) s += t; }
        wsum[lane] = s;
    }
    __syncthreads();
    int wexcl = (w == 0) ? 0 : wsum[w - 1];
    if (i < NN) g_rowptr[i] = wexcl + x - v;
    if (tid == 1023) g_bsum[blockIdx.x] = wsum[31];
}
__global__ void scan_tops() {
    int tid = threadIdx.x;
    __shared__ int sh[64];
    __shared__ int w0tot;
    int v = (tid < 49) ? g_bsum[tid] : 0;
    int lane = tid & 31, w = tid >> 5;
    int x = v;
#pragma unroll
    for (int o = 1; o < 32; o <<= 1) { int t = __shfl_up_sync(~0u, x, o); if (lane >= o) x += t; }
    if (w == 0 && lane == 31) w0tot = x;
    __syncthreads();
    int incl = x + (w == 1 ? w0tot : 0);
    sh[tid] = incl - v;
    __syncthreads();
    if (tid < 49) g_boff[tid] = sh[tid];
}
__global__ void scan_apply() {
    int i = blockIdx.x * blockDim.x + threadIdx.x;
    if (i >= NN) return;
    int rp = g_rowptr[i] + g_boff[i >> 10];
    g_rowptr[i] = rp;
    g_cursor[i] = rp;
    g_degf[i]   = (float)g_deg[i];
    if (i == 0) g_rowptr[NN] = NE;
}
__global__ void scatter_kernel(const int* __restrict__ ei) {
    int e = blockIdx.x * blockDim.x + threadIdx.x;
    if (e >= NE) return;
    int s = ei[e], d = ei[NE + e];
    int p = atomicAdd(&g_cursor[d], 1);
    g_csrc[p] = s;
    g_ceid[p] = e;
}
__global__ void eagg_kernel(const float* __restrict__ edge_attr) {
    int w = (blockIdx.x * blockDim.x + threadIdx.x) >> 5;
    if (w >= NN) return;
    int lane = threadIdx.x & 31;
    float acc = 0.f;
    int p0 = g_rowptr[w], p1 = g_rowptr[w + 1];
    for (int p = p0; p < p1; p++) {
        int e = g_ceid[p];
        acc += edge_attr[e * EDIM + lane];
    }
    g_eagg[w * EDIM + lane] = acc;
}

// ---------------- GINE aggregation ----------------
__global__ void gine_aggregate(int l) {
    int w = (blockIdx.x * blockDim.x + threadIdx.x) >> 5;
    if (w >= NN) return;
    int lane = threadIdx.x & 31;
    float4 acc = *(const float4*)&g_agg10[(size_t)l * NN * HD + (size_t)w * HD + lane * 4];
    int p0 = g_rowptr[w], p1 = g_rowptr[w + 1];
    for (int p = p0; p < p1; p++) {
        int s = g_csrc[p];
        uint2 a = *(const uint2*)&g_hnb[(size_t)s * 64 + lane * 2];
        acc.x += bf_lo(a.x); acc.y += bf_hi(a.x);
        acc.z += bf_lo(a.y); acc.w += bf_hi(a.y);
    }
    *(float4*)&g_agg[(size_t)w * HD + lane * 4] = acc;
}

// ---------------- BatchNorm scalars (self-resetting) ----------------
__global__ void bn_final(const float* __restrict__ gamma, const float* __restrict__ beta) {
    int c = threadIdx.x;
    if (c >= HD) return;
    float su = g_bnsum[c], sq = g_bnsq[c];
    g_bnsum[c] = 0.f;
    g_bnsq[c]  = 0.f;
    float mu  = su / (float)NN;
    float var = sq / (float)NN - mu * mu;
    float sc  = gamma[c] * rsqrtf(var + EPSF);
    g_scale[c] = sc;
    g_shift[c] = beta[c] - mu * sc;
}

// ---------------- GAT (features in bf16: g_hfb) ----------------
__global__ void gat_node1(const float* __restrict__ att_src, const float* __restrict__ att_dst) {
    int n = (blockIdx.x * blockDim.x + threadIdx.x) >> 5;
    if (n >= NN) return;
    int lane = threadIdx.x & 31;
    float s[4], d[4];
#pragma unroll
    for (int h = 0; h < 4; h++) {
        uint2 hp = *(const uint2*)&g_hfb[(size_t)n * 256 + h * 64 + lane * 2];
        float4 hv = { bf_lo(hp.x), bf_hi(hp.x), bf_lo(hp.y), bf_hi(hp.y) };
        float4 a1 = *(const float4*)&att_src[h * 128 + lane * 4];
        float4 a2 = *(const float4*)&att_dst[h * 128 + lane * 4];
        float ps = hv.x * a1.x + hv.y * a1.y + hv.z * a1.z + hv.w * a1.w;
        float pd = hv.x * a2.x + hv.y * a2.y + hv.z * a2.z + hv.w * a2.w;
#pragma unroll
        for (int off = 16; off > 0; off >>= 1) {
            ps += __shfl_xor_sync(0xffffffffu, ps, off);
            pd += __shfl_xor_sync(0xffffffffu, pd, off);
        }
        s[h] = ps; d[h] = pd;
    }
    if (lane == 0) {
#pragma unroll
        for (int h = 0; h < 4; h++) {
            g_as[n * 4 + h] = s[h];
            g_ad[n * 4 + h] = d[h];
        }
    }
}
__global__ void gat_node_all(const float* __restrict__ bg) {
    int n = (blockIdx.x * blockDim.x + threadIdx.x) >> 5;
    if (n >= NN) return;
    int lane = threadIdx.x & 31;
    float4 asn = *(const float4*)&g_as[n * 4];
    float4 adn = *(const float4*)&g_ad[n * 4];
    float sl0 = lrelu(asn.x + adn.x), sl1 = lrelu(asn.y + adn.y);
    float sl2 = lrelu(asn.z + adn.z), sl3 = lrelu(asn.w + adn.w);
    int p0 = g_rowptr[n], p1 = g_rowptr[n + 1];

    float m0 = sl0, m1 = sl1, m2 = sl2, m3 = sl3;
    for (int p = p0 + lane; p < p1; p += 32) {
        float4 a = *(const float4*)&g_as[g_csrc[p] * 4];
        m0 = fmaxf(m0, lrelu(a.x + adn.x)); m1 = fmaxf(m1, lrelu(a.y + adn.y));
        m2 = fmaxf(m2, lrelu(a.z + adn.z)); m3 = fmaxf(m3, lrelu(a.w + adn.w));
    }
#pragma unroll
    for (int o = 16; o > 0; o >>= 1) {
        m0 = fmaxf(m0, __shfl_xor_sync(~0u, m0, o));
        m1 = fmaxf(m1, __shfl_xor_sync(~0u, m1, o));
        m2 = fmaxf(m2, __shfl_xor_sync(~0u, m2, o));
        m3 = fmaxf(m3, __shfl_xor_sync(~0u, m3, o));
    }
    float d0 = 0.f, d1 = 0.f, d2 = 0.f, d3 = 0.f;
    for (int p = p0 + lane; p < p1; p += 32) {
        float4 a = *(const float4*)&g_as[g_csrc[p] * 4];
        d0 += __expf(lrelu(a.x + adn.x) - m0); d1 += __expf(lrelu(a.y + adn.y) - m1);
        d2 += __expf(lrelu(a.z + adn.z) - m2); d3 += __expf(lrelu(a.w + adn.w) - m3);
    }
#pragma unroll
    for (int o = 16; o > 0; o >>= 1) {
        d0 += __shfl_xor_sync(~0u, d0, o); d1 += __shfl_xor_sync(~0u, d1, o);
        d2 += __shfl_xor_sync(~0u, d2, o); d3 += __shfl_xor_sync(~0u, d3, o);
    }
    d0 += __expf(sl0 - m0); d1 += __expf(sl1 - m1);
    d2 += __expf(sl2 - m2); d3 += __expf(sl3 - m3);
    float i0 = 1.f / d0, i1 = 1.f / d1, i2 = 1.f / d2, i3 = 1.f / d3;

    float w0 = __expf(sl0 - m0) * i0, w1 = __expf(sl1 - m1) * i1;
    float w2 = __expf(sl2 - m2) * i2, w3 = __expf(sl3 - m3) * i3;
    size_t base = (size_t)n * 256 + lane * 2;
    uint2 hp0 = *(const uint2*)&g_hfb[base];
    uint2 hp1 = *(const uint2*)&g_hfb[base + 64];
    uint2 hp2 = *(const uint2*)&g_hfb[base + 128];
    uint2 hp3 = *(const uint2*)&g_hfb[base + 192];
    float4 A0 = { w0 * bf_lo(hp0.x), w0 * bf_hi(hp0.x), w0 * bf_lo(hp0.y), w0 * bf_hi(hp0.y) };
    float4 A1 = { w1 * bf_lo(hp1.x), w1 * bf_hi(hp1.x), w1 * bf_lo(hp1.y), w1 * bf_hi(hp1.y) };
    float4 A2 = { w2 * bf_lo(hp2.x), w2 * bf_hi(hp2.x), w2 * bf_lo(hp2.y), w2 * bf_hi(hp2.y) };
    float4 A3 = { w3 * bf_lo(hp3.x), w3 * bf_hi(hp3.x), w3 * bf_lo(hp3.y), w3 * bf_hi(hp3.y) };
    for (int p = p0; p < p1; p++) {
        int s = g_csrc[p];
        float4 a = *(const float4*)&g_as[s * 4];
        float e0 = __expf(lrelu(a.x + adn.x) - m0) * i0;
        float e1 = __expf(lrelu(a.y + adn.y) - m1) * i1;
        float e2 = __expf(lrelu(a.z + adn.z) - m2) * i2;
        float e3 = __expf(lrelu(a.w + adn.w) - m3) * i3;
        size_t sbx = (size_t)s * 256 + lane * 2;
        uint2 v0 = *(const uint2*)&g_hfb[sbx];
        uint2 v1 = *(const uint2*)&g_hfb[sbx + 64];
        uint2 v2 = *(const uint2*)&g_hfb[sbx + 128];
        uint2 v3 = *(const uint2*)&g_hfb[sbx + 192];
        A0.x += e0 * bf_lo(v0.x); A0.y += e0 * bf_hi(v0.x); A0.z += e0 * bf_lo(v0.y); A0.w += e0 * bf_hi(v0.y);
        A1.x += e1 * bf_lo(v1.x); A1.y += e1 * bf_hi(v1.x); A1.z += e1 * bf_lo(v1.y); A1.w += e1 * bf_hi(v1.y);
        A2.x += e2 * bf_lo(v2.x); A2.y += e2 * bf_hi(v2.x); A2.z += e2 * bf_lo(v2.y); A2.w += e2 * bf_hi(v2.y);
        A3.x += e3 * bf_lo(v3.x); A3.y += e3 * bf_hi(v3.x); A3.z += e3 * bf_lo(v3.y); A3.w += e3 * bf_hi(v3.y);
    }
    float4 bg4 = *(const float4*)&bg[lane * 4];
    float4 o4;
    o4.x = (A0.x + A1.x + A2.x + A3.x) * 0.25f + bg4.x;
    o4.y = (A0.y + A1.y + A2.y + A3.y) * 0.25f + bg4.y;
    o4.z = (A0.z + A1.z + A2.z + A3.z) * 0.25f + bg4.z;
    o4.w = (A0.w + A1.w + A2.w + A3.w) * 0.25f + bg4.w;
    *(float4*)&g_x[(size_t)n * HD + lane * 4] = o4;
}

// ---------------- pooling + fc ----------------
__device__ __forceinline__ int lbound(const int* a, int n, int key) {
    int lo = 0, hi = n;
    while (lo < hi) { int mid = (lo + hi) >> 1; if (a[mid] < key) lo = mid + 1; else hi = mid; }
    return lo;
}
__global__ void pool_kernel(const int* __restrict__ batch) {
    int g = blockIdx.x;
    int c = threadIdx.x;
    __shared__ int slo, shi;
    if (c == 0) { slo = lbound(batch, NN, g); shi = lbound(batch, NN, g + 1); }
    __syncthreads();
    int lo = slo, hi = shi;
    float a0 = 0.f, a1 = 0.f, a2 = 0.f, a3 = 0.f;
    int n = lo;
    for (; n + 4 <= hi; n += 4) {
        a0 += g_x[(size_t)n * HD + c];
        a1 += g_x[(size_t)(n + 1) * HD + c];
        a2 += g_x[(size_t)(n + 2) * HD + c];
        a3 += g_x[(size_t)(n + 3) * HD + c];
    }
    for (; n < hi; n++) a0 += g_x[(size_t)n * HD + c];
    float s = (a0 + a1) + (a2 + a3);
    g_pool[g * HD + c] = s / fmaxf((float)(hi - lo), 1.f);
}
__global__ void final_kernel(const float* __restrict__ Wfc, const float* __restrict__ bfc,
                             float* __restrict__ out) {
    int idx = blockIdx.x * blockDim.x + threadIdx.x;
    if (idx >= NG * NOUT) return;
    int g = idx / NOUT, o = idx % NOUT;
    float s = bfc[o];
#pragma unroll 8
    for (int k = 0; k < HD; k++) s += g_pool[g * HD + k] * Wfc[k * NOUT + o];
    out[idx] = s;
}

// ---------------- driver (kernel launches only — graph-capture safe) ----------------
extern "C" void kernel_launch(void* const* d_in, const int* in_sizes, int n_in,
                              void* d_out, int out_size) {
    const float* x_in      = (const float*)d_in[0];
    const float* edge_attr = (const float*)d_in[1];
    const int*   ei        = (const int*)d_in[2];
    const int*   batch     = (const int*)d_in[3];
    const float* Wn   = (const float*)d_in[4];
    const float* bn_b = (const float*)d_in[5];
    const float* We   = (const float*)d_in[6];
    const float* be_b = (const float*)d_in[7];
    const float* W1   = (const float*)d_in[8];
    const float* b1   = (const float*)d_in[9];
    const float* W2   = (const float*)d_in[10];
    const float* b2   = (const float*)d_in[11];
    const float* gamma= (const float*)d_in[12];
    const float* beta = (const float*)d_in[13];
    const float* Wg   = (const float*)d_in[14];
    const float* att_src = (const float*)d_in[15];
    const float* att_dst = (const float*)d_in[16];
    const float* bg   = (const float*)d_in[17];
    const float* Wfc  = (const float*)d_in[18];
    const float* bfc  = (const float*)d_in[19];
    float* out = (float*)d_out;

    cudaFuncSetAttribute(mma_gemm<false,false,false,true >, cudaFuncAttributeMaxDynamicSharedMemorySize, SM_TOT);
    cudaFuncSetAttribute(mma_gemm<false,true ,false,true >, cudaFuncAttributeMaxDynamicSharedMemorySize, SM_TOT);
    cudaFuncSetAttribute(mma_gemm<true ,false,false,false>, cudaFuncAttributeMaxDynamicSharedMemorySize, SM_TOT);
    cudaFuncSetAttribute(mma_gemm<false,false,true ,false>, cudaFuncAttributeMaxDynamicSharedMemorySize, SM_TOT);

    const int TB = 256;
    const int NODE_BLK = (NN + TB - 1) / TB;
    const int EDGE_BLK = (NE + TB - 1) / TB;
    const int WARP_BLK = (NN * 32 + TB - 1) / TB;
    const dim3 GEMM_G(782, 1);
    const dim3 GEMM_G4(782, 4);

    // prologue — launch index 3 is a representative GEMM (ncu samples it)
    prep_weights<<<NMAT, 256>>>(Wn, W1, W2, We, Wg);                 // 0
    zero_deg<<<NODE_BLK, TB>>>();                                    // 1
    hist_kernel<<<EDGE_BLK, TB>>>(ei);                               // 2
    mma_gemm<false,false,false,true ><<<GEMM_G, 256, SM_TOT>>>(      // 3  (profiled)
        x_in, T_NONE, 0, bn_b, T_HNB, HD);
    scan_blocks<<<49, 1024>>>();                                     // 4
    scan_tops<<<1, 64>>>();                                          // 5
    scan_apply<<<NODE_BLK, TB>>>();                                  // 6
    scatter_kernel<<<EDGE_BLK, TB>>>(ei);                            // 7
    eagg_kernel<<<WARP_BLK, TB>>>(edge_attr);                        // 8
    we_gemm<<<dim3(391, 10), 256>>>(be_b);                           // 9

    // ---- 10 GINE layers ----
    for (int l = 0; l < NL; l++) {
        if (l > 0)
            mma_gemm<false,true ,false,true ><<<GEMM_G, 256, SM_TOT>>>(
                nullptr, T_O, l, bn_b + l * HD, T_HNB, HD);
        gine_aggregate<<<WARP_BLK, TB>>>(l);
        mma_gemm<true ,false,false,false><<<GEMM_G, 256, SM_TOT>>>(
            nullptr, T_AGG, 10 + l, b1 + l * HD, T_T, HD);
        mma_gemm<false,false,true ,false><<<GEMM_G, 256, SM_TOT>>>(
            nullptr, T_T, 20 + l, b2 + l * HD, T_O, HD);
        bn_final<<<1, 128>>>(gamma + l * HD, beta + l * HD);
    }

    // ---- GAT (A-load applies layer-9 norm+relu; bf16 features out) ----
    mma_gemm<false,true ,false,true ><<<GEMM_G4, 256, SM_TOT>>>(
        nullptr, T_O, 40, nullptr, T_HFB, 512);
    gat_node1<<<WARP_BLK, TB>>>(att_src, att_dst);
    gat_node_all<<<WARP_BLK, TB>>>(bg);

    // ---- pool + fc ----
    pool_kernel<<<NG, 128>>>(batch);
    final_kernel<<<(NG * NOUT + TB - 1) / TB, TB>>>(Wfc, bfc, out);
}